// round 1
// baseline (speedup 1.0000x reference)
#include <cuda_runtime.h>
#include <math.h>

// Problem constants
#define NB 4096
#define ND 128
#define EPSF 1e-8f
#define TEMPF 11.313708498984761f   // sqrt(128)

// Scratch (device globals; no allocation allowed)
__device__ float g_qn[NB * ND];
__device__ float g_kn[NB * ND];
__device__ float g_qsq[NB];
__device__ float g_ksq[NB];

// ---------------------------------------------------------------------------
// packed f32x2 helpers (Blackwell FFMA2 path: 2x fp32 FMA throughput)
// ---------------------------------------------------------------------------
__device__ __forceinline__ unsigned long long pk2(float lo, float hi) {
    unsigned long long r;
    asm("mov.b64 %0, {%1, %2};" : "=l"(r) : "f"(lo), "f"(hi));
    return r;
}
__device__ __forceinline__ void upk2(unsigned long long v, float& lo, float& hi) {
    asm("mov.b64 {%0, %1}, %2;" : "=f"(lo), "=f"(hi) : "l"(v));
}
__device__ __forceinline__ void fma2(unsigned long long& d,
                                     unsigned long long a,
                                     unsigned long long b) {
    asm("fma.rn.f32x2 %0, %1, %2, %3;" : "=l"(d) : "l"(a), "l"(b), "l"(d));
}

// ---------------------------------------------------------------------------
// Kernel A: projection + analytic metric-norm normalization.
//   q = X @ W^T + b   (per row)
//   s = |q|^2
//   fro  = sqrt(s^2/D^2 + 2s/D + D)
//   qMq  = (s^2/D + s) / (fro + EPS)
//   qn   = q / (sqrt(qMq) + EPS);  qsq = |qn|^2
// One block handles RROWS rows; 128 threads, thread t owns output column t.
// ---------------------------------------------------------------------------
#define RROWS 16

__global__ __launch_bounds__(128) void proj_norm_kernel(
    const float* __restrict__ X, const float* __restrict__ W,
    const float* __restrict__ bias, float* __restrict__ outN,
    float* __restrict__ outSq)
{
    __shared__ float sW[ND][33];      // 32-wide k-chunk of W, padded
    __shared__ float sX[RROWS][ND];
    __shared__ float red[RROWS][ND];
    __shared__ float srow[RROWS];

    const int tid = threadIdx.x;              // 0..127 = output column
    const int i0 = blockIdx.x * RROWS;

    float acc[RROWS];
#pragma unroll
    for (int r = 0; r < RROWS; r++) acc[r] = 0.f;

#pragma unroll
    for (int e = 0; e < RROWS; e++) sX[e][tid] = X[(i0 + e) * ND + tid];

    const float bv = bias[tid];

    for (int kc = 0; kc < 4; kc++) {
        const int c = tid & 31;
        const int rbase = tid >> 5;
#pragma unroll
        for (int rr = 0; rr < 32; rr++) {
            const int r = rr * 4 + rbase;          // coalesced over c
            sW[r][c] = W[r * ND + kc * 32 + c];
        }
        __syncthreads();
#pragma unroll
        for (int cc = 0; cc < 32; cc++) {
            const float w = sW[tid][cc];
#pragma unroll
            for (int r = 0; r < RROWS; r++)
                acc[r] += sX[r][kc * 32 + cc] * w;
        }
        __syncthreads();
    }

#pragma unroll
    for (int r = 0; r < RROWS; r++) acc[r] += bv;

    // per-row sum of squares
#pragma unroll
    for (int r = 0; r < RROWS; r++) red[r][tid] = acc[r] * acc[r];
    __syncthreads();

    {
        const int w = tid >> 5, lane = tid & 31;
#pragma unroll
        for (int rr = 0; rr < RROWS / 4; rr++) {
            const int r = w * (RROWS / 4) + rr;
            float v = red[r][lane] + red[r][lane + 32] +
                      red[r][lane + 64] + red[r][lane + 96];
#pragma unroll
            for (int o = 16; o > 0; o >>= 1)
                v += __shfl_xor_sync(0xffffffffu, v, o);
            if (lane == 0) srow[r] = v;
        }
    }
    __syncthreads();

#pragma unroll
    for (int r = 0; r < RROWS; r++) {
        const float s = srow[r];
        const float invD = 1.0f / (float)ND;
        const float fro = sqrtf(s * s * invD * invD + 2.0f * s * invD + (float)ND);
        const float qmq = (s * s * invD + s) / (fro + EPSF);
        const float qnorm = sqrtf(qmq);
        const float inv = 1.0f / (qnorm + EPSF);
        outN[(i0 + r) * ND + tid] = acc[r] * inv;
        if (tid == 0) outSq[i0 + r] = s * inv * inv;
    }
}

// ---------------------------------------------------------------------------
// Kernel B: 128x128 output tile Gram (qn @ kn^T) fused with
//   d  = sqrt(max(qsq_i + ksq_j - 2 G, 0))
//   logit = TEMP / (1 + d)     -> written to out (softmaxed by kernel C)
// 256 threads, 8x8 micro-tile per thread, packed f32x2 FMAs.
// Thread (ty = tid>>4, tx = tid&15):
//   rows  i = i0 + ty + 16*r        (r = 0..7)
//   cols  j = j0 + 32*s + 2*tx + u  (s = 0..3, u = 0..1; adjacent pairs)
// ---------------------------------------------------------------------------
#define TK 32

__global__ __launch_bounds__(256, 2) void gram_sims_kernel(float* __restrict__ out)
{
    __shared__ float As[ND][TK + 1];
    __shared__ float Bs[ND][TK + 1];

    const int tid = threadIdx.x;
    const int tx = tid & 15, ty = tid >> 4;
    const int i0 = blockIdx.y * 128;
    const int j0 = blockIdx.x * 128;

    unsigned long long acc[8][4];
#pragma unroll
    for (int r = 0; r < 8; r++)
#pragma unroll
        for (int s = 0; s < 4; s++) acc[r][s] = 0ull;

    const int li = tid >> 3;       // 0..31
    const int lk4 = tid & 7;       // 0..7  (float4 index within 32-chunk)

    for (int kc = 0; kc < ND / TK; kc++) {
#pragma unroll
        for (int p = 0; p < 4; p++) {
            const int i = li + p * 32;
            float4 va = *(const float4*)&g_qn[(i0 + i) * ND + kc * TK + lk4 * 4];
            float4 vb = *(const float4*)&g_kn[(j0 + i) * ND + kc * TK + lk4 * 4];
            As[i][lk4 * 4 + 0] = va.x; As[i][lk4 * 4 + 1] = va.y;
            As[i][lk4 * 4 + 2] = va.z; As[i][lk4 * 4 + 3] = va.w;
            Bs[i][lk4 * 4 + 0] = vb.x; Bs[i][lk4 * 4 + 1] = vb.y;
            Bs[i][lk4 * 4 + 2] = vb.z; Bs[i][lk4 * 4 + 3] = vb.w;
        }
        __syncthreads();

#pragma unroll
        for (int k = 0; k < TK; k++) {
            unsigned long long a2[8], b2[4];
#pragma unroll
            for (int r = 0; r < 8; r++) {
                const float a = As[ty + r * 16][k];
                a2[r] = pk2(a, a);
            }
#pragma unroll
            for (int s = 0; s < 4; s++) {
                const float b0 = Bs[32 * s + 2 * tx + 0][k];
                const float b1 = Bs[32 * s + 2 * tx + 1][k];
                b2[s] = pk2(b0, b1);
            }
#pragma unroll
            for (int r = 0; r < 8; r++)
#pragma unroll
                for (int s = 0; s < 4; s++)
                    fma2(acc[r][s], a2[r], b2[s]);
        }
        __syncthreads();
    }

    // epilogue: distances -> logits
    float qs[8];
#pragma unroll
    for (int r = 0; r < 8; r++) qs[r] = g_qsq[i0 + ty + 16 * r];

#pragma unroll
    for (int s = 0; s < 4; s++) {
        const int j = j0 + 32 * s + 2 * tx;
        const float ks0 = g_ksq[j];
        const float ks1 = g_ksq[j + 1];
#pragma unroll
        for (int r = 0; r < 8; r++) {
            float g0, g1;
            upk2(acc[r][s], g0, g1);
            float d20 = fmaxf(qs[r] + ks0 - 2.0f * g0, 0.0f);
            float d21 = fmaxf(qs[r] + ks1 - 2.0f * g1, 0.0f);
            float l0 = TEMPF / (1.0f + sqrtf(d20));
            float l1 = TEMPF / (1.0f + sqrtf(d21));
            float2 st = make_float2(l0, l1);
            *(float2*)&out[(size_t)(i0 + ty + 16 * r) * NB + j] = st;
        }
    }
}

// ---------------------------------------------------------------------------
// Kernel C: in-place row softmax over 4096 columns.
// One block (256 threads) per row; row held in registers (4 float4 / thread).
// ---------------------------------------------------------------------------
__global__ __launch_bounds__(256) void softmax_kernel(float* __restrict__ out)
{
    __shared__ float sred[8];
    const int row = blockIdx.x;
    const int tid = threadIdx.x;
    const int lane = tid & 31, warp = tid >> 5;

    float4* p = (float4*)(out + (size_t)row * NB);
    float4 v[4];
#pragma unroll
    for (int q = 0; q < 4; q++) v[q] = p[tid + q * 256];

    // max
    float m = -1e30f;
#pragma unroll
    for (int q = 0; q < 4; q++) {
        m = fmaxf(m, fmaxf(fmaxf(v[q].x, v[q].y), fmaxf(v[q].z, v[q].w)));
    }
#pragma unroll
    for (int o = 16; o > 0; o >>= 1) m = fmaxf(m, __shfl_xor_sync(0xffffffffu, m, o));
    if (lane == 0) sred[warp] = m;
    __syncthreads();
    m = sred[0];
#pragma unroll
    for (int w = 1; w < 8; w++) m = fmaxf(m, sred[w]);
    __syncthreads();

    // exp + sum
    float sum = 0.f;
#pragma unroll
    for (int q = 0; q < 4; q++) {
        v[q].x = __expf(v[q].x - m); v[q].y = __expf(v[q].y - m);
        v[q].z = __expf(v[q].z - m); v[q].w = __expf(v[q].w - m);
        sum += v[q].x + v[q].y + v[q].z + v[q].w;
    }
#pragma unroll
    for (int o = 16; o > 0; o >>= 1) sum += __shfl_xor_sync(0xffffffffu, sum, o);
    if (lane == 0) sred[warp] = sum;
    __syncthreads();
    sum = sred[0] + sred[1] + sred[2] + sred[3] +
          sred[4] + sred[5] + sred[6] + sred[7];

    const float inv = 1.0f / sum;
#pragma unroll
    for (int q = 0; q < 4; q++) {
        v[q].x *= inv; v[q].y *= inv; v[q].z *= inv; v[q].w *= inv;
        p[tid + q * 256] = v[q];
    }
}

// ---------------------------------------------------------------------------
// Launch
// Inputs (metadata order): 0 query_points [4096,128], 1 key_points [4096,128],
//                          2 Wq [128,128], 3 bq [128], 4 Wk [128,128], 5 bk [128]
// Output: float32 [4096,4096]
// ---------------------------------------------------------------------------
extern "C" void kernel_launch(void* const* d_in, const int* in_sizes, int n_in,
                              void* d_out, int out_size)
{
    (void)in_sizes; (void)n_in; (void)out_size;
    const float* qp = (const float*)d_in[0];
    const float* kp = (const float*)d_in[1];
    const float* Wq = (const float*)d_in[2];
    const float* bq = (const float*)d_in[3];
    const float* Wk = (const float*)d_in[4];
    const float* bk = (const float*)d_in[5];
    float* out = (float*)d_out;

    float* qn;  cudaGetSymbolAddress((void**)&qn,  g_qn);
    float* kn;  cudaGetSymbolAddress((void**)&kn,  g_kn);
    float* qsq; cudaGetSymbolAddress((void**)&qsq, g_qsq);
    float* ksq; cudaGetSymbolAddress((void**)&ksq, g_ksq);

    proj_norm_kernel<<<NB / RROWS, 128>>>(qp, Wq, bq, qn, qsq);
    proj_norm_kernel<<<NB / RROWS, 128>>>(kp, Wk, bk, kn, ksq);

    dim3 g(NB / 128, NB / 128);
    gram_sims_kernel<<<g, 256>>>(out);

    softmax_kernel<<<NB, 256>>>(out);
}

// round 3
// speedup vs baseline: 1.4023x; 1.4023x over previous
#include <cuda_runtime.h>
#include <cuda_bf16.h>
#include <math.h>
#include <stdint.h>

// Problem constants
#define NB 4096
#define ND 128
#define EPSF 1e-8f
#define TEMPF 11.313708498984761f   // sqrt(128)

// Scratch (device globals; no allocation allowed)
__device__ __nv_bfloat16 g_qn_hi[NB * ND];
__device__ __nv_bfloat16 g_qn_lo[NB * ND];
__device__ __nv_bfloat16 g_kn_hi[NB * ND];
__device__ __nv_bfloat16 g_kn_lo[NB * ND];
__device__ float g_qsq[NB];
__device__ float g_ksq[NB];

// ---------------------------------------------------------------------------
// PTX helpers (base compute_103 — NO sm_103a-only instructions)
// ---------------------------------------------------------------------------
__device__ __forceinline__ uint32_t smem_u32(const void* p) {
    uint32_t a;
    asm("{ .reg .u64 t; cvta.to.shared.u64 t, %1; cvt.u32.u64 %0, t; }"
        : "=r"(a) : "l"(p));
    return a;
}

__device__ __forceinline__ void ldsm4(uint32_t* r, uint32_t addr) {
    asm volatile("ldmatrix.sync.aligned.m8n8.x4.shared.b16 {%0,%1,%2,%3}, [%4];"
                 : "=r"(r[0]), "=r"(r[1]), "=r"(r[2]), "=r"(r[3]) : "r"(addr));
}

__device__ __forceinline__ void mma_bf16(float* c, const uint32_t* a,
                                         const uint32_t* b) {
    asm volatile(
        "mma.sync.aligned.m16n8k16.row.col.f32.bf16.bf16.f32 "
        "{%0,%1,%2,%3}, {%4,%5,%6,%7}, {%8,%9}, {%0,%1,%2,%3};"
        : "+f"(c[0]), "+f"(c[1]), "+f"(c[2]), "+f"(c[3])
        : "r"(a[0]), "r"(a[1]), "r"(a[2]), "r"(a[3]), "r"(b[0]), "r"(b[1]));
}

// ---------------------------------------------------------------------------
// Kernel A: projection + analytic metric-norm normalization.
// Emits bf16 hi/lo split of the normalized rows (for compensated HMMA) and
// the squared norms.
// ---------------------------------------------------------------------------
#define RROWS 16

__global__ __launch_bounds__(128) void proj_norm_kernel(
    const float* __restrict__ X, const float* __restrict__ W,
    const float* __restrict__ bias,
    __nv_bfloat16* __restrict__ outH, __nv_bfloat16* __restrict__ outL,
    float* __restrict__ outSq)
{
    __shared__ float sW[ND][33];
    __shared__ float sX[RROWS][ND];
    __shared__ float red[RROWS][ND];
    __shared__ float srow[RROWS];

    const int tid = threadIdx.x;
    const int i0 = blockIdx.x * RROWS;

    float acc[RROWS];
#pragma unroll
    for (int r = 0; r < RROWS; r++) acc[r] = 0.f;

#pragma unroll
    for (int e = 0; e < RROWS; e++) sX[e][tid] = X[(i0 + e) * ND + tid];

    const float bv = bias[tid];

    for (int kc = 0; kc < 4; kc++) {
        const int c = tid & 31;
        const int rbase = tid >> 5;
#pragma unroll
        for (int rr = 0; rr < 32; rr++) {
            const int r = rr * 4 + rbase;
            sW[r][c] = W[r * ND + kc * 32 + c];
        }
        __syncthreads();
#pragma unroll
        for (int cc = 0; cc < 32; cc++) {
            const float w = sW[tid][cc];
#pragma unroll
            for (int r = 0; r < RROWS; r++)
                acc[r] += sX[r][kc * 32 + cc] * w;
        }
        __syncthreads();
    }

#pragma unroll
    for (int r = 0; r < RROWS; r++) acc[r] += bv;

#pragma unroll
    for (int r = 0; r < RROWS; r++) red[r][tid] = acc[r] * acc[r];
    __syncthreads();

    {
        const int w = tid >> 5, lane = tid & 31;
#pragma unroll
        for (int rr = 0; rr < RROWS / 4; rr++) {
            const int r = w * (RROWS / 4) + rr;
            float v = red[r][lane] + red[r][lane + 32] +
                      red[r][lane + 64] + red[r][lane + 96];
#pragma unroll
            for (int o = 16; o > 0; o >>= 1)
                v += __shfl_xor_sync(0xffffffffu, v, o);
            if (lane == 0) srow[r] = v;
        }
    }
    __syncthreads();

#pragma unroll
    for (int r = 0; r < RROWS; r++) {
        const float s = srow[r];
        const float invD = 1.0f / (float)ND;
        const float fro = sqrtf(s * s * invD * invD + 2.0f * s * invD + (float)ND);
        const float qmq = (s * s * invD + s) / (fro + EPSF);
        const float qnorm = sqrtf(qmq);
        const float inv = 1.0f / (qnorm + EPSF);
        const float v = acc[r] * inv;
        const __nv_bfloat16 h = __float2bfloat16(v);
        const __nv_bfloat16 l = __float2bfloat16(v - __bfloat162float(h));
        outH[(i0 + r) * ND + tid] = h;
        outL[(i0 + r) * ND + tid] = l;
        if (tid == 0) outSq[i0 + r] = s * inv * inv;
    }
}

// ---------------------------------------------------------------------------
// Kernel B: compensated bf16 HMMA Gram + fused exp-logit epilogue.
// CTA: 128x128 tile, 8 warps in 4(M) x 2(N); warp tile 32x64.
// acc += Ahi*Bhi + Alo*Bhi + Ahi*Blo  (fp32 accum; lo*lo dropped ~2^-18)
// Epilogue: d2 = qsq+ksq-2G; write exp(TEMP/(1+sqrt(d2))).
// ---------------------------------------------------------------------------
#define KC 32
#define SSTRIDE 40   // bf16 elements per smem row (5 x 16B units, odd -> conflict-free)

__global__ __launch_bounds__(256) void gram_exp_kernel(float* __restrict__ out)
{
    __shared__ __align__(16) __nv_bfloat16 As_hi[128][SSTRIDE];
    __shared__ __align__(16) __nv_bfloat16 As_lo[128][SSTRIDE];
    __shared__ __align__(16) __nv_bfloat16 Bs_hi[128][SSTRIDE];
    __shared__ __align__(16) __nv_bfloat16 Bs_lo[128][SSTRIDE];
    __shared__ float ks_s[128];
    __shared__ float qs_s[128];

    const int tid = threadIdx.x;
    const int lane = tid & 31;
    const int w = tid >> 5;
    const int wm = w & 3;        // M quarter (32 rows)
    const int wn = w >> 2;       // N half (64 cols)
    const int i0 = blockIdx.y * 128;
    const int j0 = blockIdx.x * 128;

    if (tid < 128) ks_s[tid] = g_ksq[j0 + tid];
    else           qs_s[tid - 128] = g_qsq[i0 + tid - 128];

    float acc[2][8][4];
#pragma unroll
    for (int mt = 0; mt < 2; mt++)
#pragma unroll
        for (int n8 = 0; n8 < 8; n8++)
#pragma unroll
            for (int q = 0; q < 4; q++) acc[mt][n8][q] = 0.f;

    // ldmatrix lane address components
    const int a_row = lane & 15;
    const int a_kh = lane >> 4;                       // 0/1 -> k half
    const int b_n = (lane & 7) | ((lane >> 1) & 8);   // n within 16
    const int b_kh = (lane >> 3) & 1;

    const uint32_t ashi = smem_u32(As_hi);
    const uint32_t aslo = smem_u32(As_lo);
    const uint32_t bshi = smem_u32(Bs_hi);
    const uint32_t bslo = smem_u32(Bs_lo);

    const int ld_row = tid >> 2;       // 0..63  (x2 iterations -> 128 rows)
    const int ld_seg = tid & 3;        // 8-bf16 segment within 32-col chunk

    for (int kc = 0; kc < 4; kc++) {
        const int c0 = kc * KC;
#pragma unroll
        for (int it = 0; it < 2; it++) {
            const int row = it * 64 + ld_row;
            const size_t gidx = (size_t)(i0 + row) * ND + c0 + ld_seg * 8;
            const size_t gjdx = (size_t)(j0 + row) * ND + c0 + ld_seg * 8;
            *(uint4*)&As_hi[row][ld_seg * 8] = *(const uint4*)&g_qn_hi[gidx];
            *(uint4*)&As_lo[row][ld_seg * 8] = *(const uint4*)&g_qn_lo[gidx];
            *(uint4*)&Bs_hi[row][ld_seg * 8] = *(const uint4*)&g_kn_hi[gjdx];
            *(uint4*)&Bs_lo[row][ld_seg * 8] = *(const uint4*)&g_kn_lo[gjdx];
        }
        __syncthreads();

#pragma unroll
        for (int ks = 0; ks < 2; ks++) {
            const int k0 = ks * 16;
            const uint32_t a_off =
                (uint32_t)(((wm * 32 + a_row) * SSTRIDE + k0 + a_kh * 8) * 2);
            const uint32_t b_off0 =
                (uint32_t)(((wn * 64 + b_n) * SSTRIDE + k0 + b_kh * 8) * 2);

            uint32_t ahi[2][4], alo[2][4], bf[4][4];
#pragma unroll
            for (int mt = 0; mt < 2; mt++) {
                ldsm4(ahi[mt], ashi + a_off + (uint32_t)(mt * 16 * SSTRIDE * 2));
                ldsm4(alo[mt], aslo + a_off + (uint32_t)(mt * 16 * SSTRIDE * 2));
            }
            // B hi: hihi + lohi
#pragma unroll
            for (int nt = 0; nt < 4; nt++)
                ldsm4(bf[nt], bshi + b_off0 + (uint32_t)(nt * 16 * SSTRIDE * 2));
#pragma unroll
            for (int mt = 0; mt < 2; mt++)
#pragma unroll
                for (int nt = 0; nt < 4; nt++) {
                    mma_bf16(acc[mt][nt * 2 + 0], ahi[mt], &bf[nt][0]);
                    mma_bf16(acc[mt][nt * 2 + 1], ahi[mt], &bf[nt][2]);
                    mma_bf16(acc[mt][nt * 2 + 0], alo[mt], &bf[nt][0]);
                    mma_bf16(acc[mt][nt * 2 + 1], alo[mt], &bf[nt][2]);
                }
            // B lo: hilo
#pragma unroll
            for (int nt = 0; nt < 4; nt++)
                ldsm4(bf[nt], bslo + b_off0 + (uint32_t)(nt * 16 * SSTRIDE * 2));
#pragma unroll
            for (int mt = 0; mt < 2; mt++)
#pragma unroll
                for (int nt = 0; nt < 4; nt++) {
                    mma_bf16(acc[mt][nt * 2 + 0], ahi[mt], &bf[nt][0]);
                    mma_bf16(acc[mt][nt * 2 + 1], ahi[mt], &bf[nt][2]);
                }
        }
        __syncthreads();
    }

    // Epilogue: C frag (m16n8): c0,c1 -> row lane/4, cols 2*(lane%4)+{0,1};
    //           c2,c3 -> row+8.
    const int rq = lane >> 2;
    const int cq = (lane & 3) * 2;
#pragma unroll
    for (int mt = 0; mt < 2; mt++) {
        const int rl0 = wm * 32 + mt * 16 + rq;       // local row (low)
        const float qs0 = qs_s[rl0];
        const float qs1 = qs_s[rl0 + 8];
#pragma unroll
        for (int n8 = 0; n8 < 8; n8++) {
            const int cl = wn * 64 + n8 * 8 + cq;     // local col
            const float k0v = ks_s[cl], k1v = ks_s[cl + 1];
            const float* a = acc[mt][n8];

            float d00 = fmaxf(qs0 + k0v - 2.0f * a[0], 0.0f);
            float d01 = fmaxf(qs0 + k1v - 2.0f * a[1], 0.0f);
            float d10 = fmaxf(qs1 + k0v - 2.0f * a[2], 0.0f);
            float d11 = fmaxf(qs1 + k1v - 2.0f * a[3], 0.0f);

            float2 e0, e1;
            e0.x = __expf(TEMPF / (1.0f + sqrtf(d00)));
            e0.y = __expf(TEMPF / (1.0f + sqrtf(d01)));
            e1.x = __expf(TEMPF / (1.0f + sqrtf(d10)));
            e1.y = __expf(TEMPF / (1.0f + sqrtf(d11)));

            *(float2*)&out[(size_t)(i0 + rl0) * NB + j0 + cl] = e0;
            *(float2*)&out[(size_t)(i0 + rl0 + 8) * NB + j0 + cl] = e1;
        }
    }
}

// ---------------------------------------------------------------------------
// Kernel C: row sum + normalize (values already exp'd; no max needed).
// ---------------------------------------------------------------------------
__global__ __launch_bounds__(256) void scale_kernel(float* __restrict__ out)
{
    __shared__ float sred[8];
    const int row = blockIdx.x;
    const int tid = threadIdx.x;
    const int lane = tid & 31, warp = tid >> 5;

    float4* p = (float4*)(out + (size_t)row * NB);
    float4 v[4];
#pragma unroll
    for (int q = 0; q < 4; q++) v[q] = p[tid + q * 256];

    float sum = 0.f;
#pragma unroll
    for (int q = 0; q < 4; q++)
        sum += (v[q].x + v[q].y) + (v[q].z + v[q].w);
#pragma unroll
    for (int o = 16; o > 0; o >>= 1) sum += __shfl_xor_sync(0xffffffffu, sum, o);
    if (lane == 0) sred[warp] = sum;
    __syncthreads();
    sum = sred[0] + sred[1] + sred[2] + sred[3] +
          sred[4] + sred[5] + sred[6] + sred[7];

    const float inv = 1.0f / sum;
#pragma unroll
    for (int q = 0; q < 4; q++) {
        v[q].x *= inv; v[q].y *= inv; v[q].z *= inv; v[q].w *= inv;
        p[tid + q * 256] = v[q];
    }
}

// ---------------------------------------------------------------------------
// Launch
// ---------------------------------------------------------------------------
extern "C" void kernel_launch(void* const* d_in, const int* in_sizes, int n_in,
                              void* d_out, int out_size)
{
    (void)in_sizes; (void)n_in; (void)out_size;
    const float* qp = (const float*)d_in[0];
    const float* kp = (const float*)d_in[1];
    const float* Wq = (const float*)d_in[2];
    const float* bq = (const float*)d_in[3];
    const float* Wk = (const float*)d_in[4];
    const float* bk = (const float*)d_in[5];
    float* out = (float*)d_out;

    __nv_bfloat16 *qnh, *qnl, *knh, *knl;
    float *qsq, *ksq;
    cudaGetSymbolAddress((void**)&qnh, g_qn_hi);
    cudaGetSymbolAddress((void**)&qnl, g_qn_lo);
    cudaGetSymbolAddress((void**)&knh, g_kn_hi);
    cudaGetSymbolAddress((void**)&knl, g_kn_lo);
    cudaGetSymbolAddress((void**)&qsq, g_qsq);
    cudaGetSymbolAddress((void**)&ksq, g_ksq);

    proj_norm_kernel<<<NB / RROWS, 128>>>(qp, Wq, bq, qnh, qnl, qsq);
    proj_norm_kernel<<<NB / RROWS, 128>>>(kp, Wk, bk, knh, knl, ksq);

    dim3 g(NB / 128, NB / 128);
    gram_exp_kernel<<<g, 256>>>(out);

    scale_kernel<<<NB, 256>>>(out);
}

// round 4
// speedup vs baseline: 1.9456x; 1.3875x over previous
#include <cuda_runtime.h>
#include <cuda_bf16.h>
#include <math.h>
#include <stdint.h>

// Problem constants
#define NB 4096
#define ND 128
#define EPSF 1e-8f
#define TEMPF 11.313708498984761f   // sqrt(128)

// Scratch (device globals; no allocation allowed)
__device__ __nv_bfloat16 g_qn_hi[NB * ND];
__device__ __nv_bfloat16 g_qn_lo[NB * ND];
__device__ __nv_bfloat16 g_kn_hi[NB * ND];
__device__ __nv_bfloat16 g_kn_lo[NB * ND];
__device__ float g_qsq[NB];
__device__ float g_ksq[NB];

// ---------------------------------------------------------------------------
// PTX helpers (base compute_103 — NO sm_103a-only instructions)
// ---------------------------------------------------------------------------
__device__ __forceinline__ uint32_t smem_u32(const void* p) {
    uint32_t a;
    asm("{ .reg .u64 t; cvta.to.shared.u64 t, %1; cvt.u32.u64 %0, t; }"
        : "=r"(a) : "l"(p));
    return a;
}

__device__ __forceinline__ void ldsm4(uint32_t* r, uint32_t addr) {
    asm volatile("ldmatrix.sync.aligned.m8n8.x4.shared.b16 {%0,%1,%2,%3}, [%4];"
                 : "=r"(r[0]), "=r"(r[1]), "=r"(r[2]), "=r"(r[3]) : "r"(addr));
}

__device__ __forceinline__ void mma_bf16(float* c, const uint32_t* a,
                                         const uint32_t* b) {
    asm volatile(
        "mma.sync.aligned.m16n8k16.row.col.f32.bf16.bf16.f32 "
        "{%0,%1,%2,%3}, {%4,%5,%6,%7}, {%8,%9}, {%0,%1,%2,%3};"
        : "+f"(c[0]), "+f"(c[1]), "+f"(c[2]), "+f"(c[3])
        : "r"(a[0]), "r"(a[1]), "r"(a[2]), "r"(a[3]), "r"(b[0]), "r"(b[1]));
}

__device__ __forceinline__ void cp16(uint32_t s, const void* g) {
    asm volatile("cp.async.cg.shared.global [%0], [%1], 16;" :: "r"(s), "l"(g));
}
__device__ __forceinline__ void cp_commit() {
    asm volatile("cp.async.commit_group;" ::: "memory");
}
__device__ __forceinline__ void cp_wait1() {
    asm volatile("cp.async.wait_group 1;" ::: "memory");
}
__device__ __forceinline__ void cp_wait0() {
    asm volatile("cp.async.wait_group 0;" ::: "memory");
}

// ---------------------------------------------------------------------------
// Kernel A: projection + analytic metric-norm normalization (q and k fused;
// blockIdx.y selects which). Emits bf16 hi/lo split + squared norms.
// ---------------------------------------------------------------------------
#define RROWS 16

__global__ __launch_bounds__(128) void proj_norm_kernel(
    const float* __restrict__ Xq, const float* __restrict__ Wq,
    const float* __restrict__ bq,
    const float* __restrict__ Xk, const float* __restrict__ Wk,
    const float* __restrict__ bk,
    __nv_bfloat16* __restrict__ qH, __nv_bfloat16* __restrict__ qL,
    float* __restrict__ qSq,
    __nv_bfloat16* __restrict__ kH, __nv_bfloat16* __restrict__ kL,
    float* __restrict__ kSq)
{
    const int which = blockIdx.y;
    const float* X = which ? Xk : Xq;
    const float* W = which ? Wk : Wq;
    const float* bias = which ? bk : bq;
    __nv_bfloat16* outH = which ? kH : qH;
    __nv_bfloat16* outL = which ? kL : qL;
    float* outSq = which ? kSq : qSq;

    __shared__ float sW[ND][33];
    __shared__ float sX[RROWS][ND];
    __shared__ float red[RROWS][ND];
    __shared__ float srow[RROWS];

    const int tid = threadIdx.x;
    const int i0 = blockIdx.x * RROWS;

    float acc[RROWS];
#pragma unroll
    for (int r = 0; r < RROWS; r++) acc[r] = 0.f;

#pragma unroll
    for (int e = 0; e < RROWS; e++) sX[e][tid] = X[(i0 + e) * ND + tid];

    const float bv = bias[tid];

    for (int kc = 0; kc < 4; kc++) {
        const int c = tid & 31;
        const int rbase = tid >> 5;
#pragma unroll
        for (int rr = 0; rr < 32; rr++) {
            const int r = rr * 4 + rbase;
            sW[r][c] = W[r * ND + kc * 32 + c];
        }
        __syncthreads();
#pragma unroll
        for (int cc = 0; cc < 32; cc++) {
            const float w = sW[tid][cc];
#pragma unroll
            for (int r = 0; r < RROWS; r++)
                acc[r] += sX[r][kc * 32 + cc] * w;
        }
        __syncthreads();
    }

#pragma unroll
    for (int r = 0; r < RROWS; r++) acc[r] += bv;

#pragma unroll
    for (int r = 0; r < RROWS; r++) red[r][tid] = acc[r] * acc[r];
    __syncthreads();

    {
        const int w = tid >> 5, lane = tid & 31;
#pragma unroll
        for (int rr = 0; rr < RROWS / 4; rr++) {
            const int r = w * (RROWS / 4) + rr;
            float v = red[r][lane] + red[r][lane + 32] +
                      red[r][lane + 64] + red[r][lane + 96];
#pragma unroll
            for (int o = 16; o > 0; o >>= 1)
                v += __shfl_xor_sync(0xffffffffu, v, o);
            if (lane == 0) srow[r] = v;
        }
    }
    __syncthreads();

#pragma unroll
    for (int r = 0; r < RROWS; r++) {
        const float s = srow[r];
        const float invD = 1.0f / (float)ND;
        const float fro = sqrtf(s * s * invD * invD + 2.0f * s * invD + (float)ND);
        const float qmq = (s * s * invD + s) / (fro + EPSF);
        const float qnorm = sqrtf(qmq);
        const float inv = 1.0f / (qnorm + EPSF);
        const float v = acc[r] * inv;
        const __nv_bfloat16 h = __float2bfloat16(v);
        const __nv_bfloat16 l = __float2bfloat16(v - __bfloat162float(h));
        outH[(i0 + r) * ND + tid] = h;
        outL[(i0 + r) * ND + tid] = l;
        if (tid == 0) outSq[i0 + r] = s * inv * inv;
    }
}

// ---------------------------------------------------------------------------
// Kernel B: compensated bf16 HMMA Gram + fused exp-logit epilogue.
// cp.async 2-stage pipeline over 4 K=32 chunks (double-buffered dyn smem).
// CTA: 128x128 tile, 8 warps (4M x 2N), warp tile 32x64.
// acc += Ahi*Bhi + Alo*Bhi + Ahi*Blo (fp32 accum; lo*lo dropped ~2^-18).
// Epilogue: d2 = qsq+ksq-2G; write exp(TEMP/(1+sqrt(d2))).
// ---------------------------------------------------------------------------
#define SSTRIDE 40                 // bf16 elems per smem row (80 B, 16B-aligned, odd#banks)
#define MAT_BYTES 10240            // 128 rows * 80 B
#define STAGE_BYTES (4 * MAT_BYTES)
#define GRAM_SMEM (2 * STAGE_BYTES)   // 81920

__device__ __forceinline__ void issue_chunk(uint32_t sbase, int st, int kc,
                                            int i0, int j0, int tid)
{
    const uint32_t stb = sbase + (uint32_t)(st * STAGE_BYTES);
#pragma unroll
    for (int it = 0; it < 2; it++) {
        const int t = it * 256 + tid;      // 0..511
        const int row = t >> 2;
        const int seg = t & 3;
        const uint32_t soff = (uint32_t)(row * 80 + seg * 16);
        const size_t gi = (size_t)(i0 + row) * ND + kc * 32 + seg * 8;
        const size_t gj = (size_t)(j0 + row) * ND + kc * 32 + seg * 8;
        cp16(stb + 0 * MAT_BYTES + soff, &g_qn_hi[gi]);
        cp16(stb + 1 * MAT_BYTES + soff, &g_qn_lo[gi]);
        cp16(stb + 2 * MAT_BYTES + soff, &g_kn_hi[gj]);
        cp16(stb + 3 * MAT_BYTES + soff, &g_kn_lo[gj]);
    }
}

__global__ __launch_bounds__(256, 2) void gram_exp_kernel(float* __restrict__ out)
{
    extern __shared__ __align__(16) char dsm[];
    __shared__ float ks_s[128];
    __shared__ float qs_s[128];

    const int tid = threadIdx.x;
    const int lane = tid & 31;
    const int w = tid >> 5;
    const int wm = w & 3;        // M quarter (32 rows)
    const int wn = w >> 2;       // N half (64 cols)
    const int i0 = blockIdx.y * 128;
    const int j0 = blockIdx.x * 128;

    if (tid < 128) ks_s[tid] = g_ksq[j0 + tid];
    else           qs_s[tid - 128] = g_qsq[i0 + tid - 128];

    const uint32_t sbase = smem_u32(dsm);

    issue_chunk(sbase, 0, 0, i0, j0, tid); cp_commit();
    issue_chunk(sbase, 1, 1, i0, j0, tid); cp_commit();

    float acc[2][8][4];
#pragma unroll
    for (int mt = 0; mt < 2; mt++)
#pragma unroll
        for (int n8 = 0; n8 < 8; n8++)
#pragma unroll
            for (int q = 0; q < 4; q++) acc[mt][n8][q] = 0.f;

    // ldmatrix lane address components
    const int a_row = lane & 15;
    const int a_kh = lane >> 4;
    const int b_n = (lane & 7) | ((lane >> 1) & 8);
    const int b_kh = (lane >> 3) & 1;

#pragma unroll
    for (int kc = 0; kc < 4; kc++) {
        if (kc < 3) cp_wait1(); else cp_wait0();
        __syncthreads();

        const uint32_t stb = sbase + (uint32_t)((kc & 1) * STAGE_BYTES);
        const uint32_t ashi = stb + 0 * MAT_BYTES;
        const uint32_t aslo = stb + 1 * MAT_BYTES;
        const uint32_t bshi = stb + 2 * MAT_BYTES;
        const uint32_t bslo = stb + 3 * MAT_BYTES;

#pragma unroll
        for (int ks = 0; ks < 2; ks++) {
            const int k0 = ks * 16;
            const uint32_t a_off =
                (uint32_t)(((wm * 32 + a_row) * SSTRIDE + k0 + a_kh * 8) * 2);
            const uint32_t b_off0 =
                (uint32_t)(((wn * 64 + b_n) * SSTRIDE + k0 + b_kh * 8) * 2);

            uint32_t ahi[2][4], alo[2][4], bf[4][4];
#pragma unroll
            for (int mt = 0; mt < 2; mt++) {
                ldsm4(ahi[mt], ashi + a_off + (uint32_t)(mt * 16 * SSTRIDE * 2));
                ldsm4(alo[mt], aslo + a_off + (uint32_t)(mt * 16 * SSTRIDE * 2));
            }
            // B hi: hihi + lohi
#pragma unroll
            for (int nt = 0; nt < 4; nt++)
                ldsm4(bf[nt], bshi + b_off0 + (uint32_t)(nt * 16 * SSTRIDE * 2));
#pragma unroll
            for (int mt = 0; mt < 2; mt++)
#pragma unroll
                for (int nt = 0; nt < 4; nt++) {
                    mma_bf16(acc[mt][nt * 2 + 0], ahi[mt], &bf[nt][0]);
                    mma_bf16(acc[mt][nt * 2 + 1], ahi[mt], &bf[nt][2]);
                    mma_bf16(acc[mt][nt * 2 + 0], alo[mt], &bf[nt][0]);
                    mma_bf16(acc[mt][nt * 2 + 1], alo[mt], &bf[nt][2]);
                }
            // B lo: hilo
#pragma unroll
            for (int nt = 0; nt < 4; nt++)
                ldsm4(bf[nt], bslo + b_off0 + (uint32_t)(nt * 16 * SSTRIDE * 2));
#pragma unroll
            for (int mt = 0; mt < 2; mt++)
#pragma unroll
                for (int nt = 0; nt < 4; nt++) {
                    mma_bf16(acc[mt][nt * 2 + 0], ahi[mt], &bf[nt][0]);
                    mma_bf16(acc[mt][nt * 2 + 1], ahi[mt], &bf[nt][2]);
                }
        }
        __syncthreads();
        if (kc < 2) { issue_chunk(sbase, kc & 1, kc + 2, i0, j0, tid); cp_commit(); }
    }

    // Epilogue: C frag (m16n8): c0,c1 -> row lane/4, cols 2*(lane%4)+{0,1};
    //           c2,c3 -> row+8.
    const int rq = lane >> 2;
    const int cq = (lane & 3) * 2;
#pragma unroll
    for (int mt = 0; mt < 2; mt++) {
        const int rl0 = wm * 32 + mt * 16 + rq;
        const float qs0 = qs_s[rl0];
        const float qs1 = qs_s[rl0 + 8];
#pragma unroll
        for (int n8 = 0; n8 < 8; n8++) {
            const int cl = wn * 64 + n8 * 8 + cq;
            const float k0v = ks_s[cl], k1v = ks_s[cl + 1];
            const float* a = acc[mt][n8];

            float d00 = fmaxf(qs0 + k0v - 2.0f * a[0], 0.0f);
            float d01 = fmaxf(qs0 + k1v - 2.0f * a[1], 0.0f);
            float d10 = fmaxf(qs1 + k0v - 2.0f * a[2], 0.0f);
            float d11 = fmaxf(qs1 + k1v - 2.0f * a[3], 0.0f);

            float2 e0, e1;
            e0.x = __expf(TEMPF / (1.0f + sqrtf(d00)));
            e0.y = __expf(TEMPF / (1.0f + sqrtf(d01)));
            e1.x = __expf(TEMPF / (1.0f + sqrtf(d10)));
            e1.y = __expf(TEMPF / (1.0f + sqrtf(d11)));

            *(float2*)&out[(size_t)(i0 + rl0) * NB + j0 + cl] = e0;
            *(float2*)&out[(size_t)(i0 + rl0 + 8) * NB + j0 + cl] = e1;
        }
    }
}

// ---------------------------------------------------------------------------
// Kernel C: row sum + normalize, 2 rows per block (deep MLP for latency).
// ---------------------------------------------------------------------------
__global__ __launch_bounds__(256) void scale_kernel(float* __restrict__ out)
{
    __shared__ float sred0[8];
    __shared__ float sred1[8];
    const int row0 = blockIdx.x * 2;
    const int tid = threadIdx.x;
    const int lane = tid & 31, warp = tid >> 5;

    float4* p0 = (float4*)(out + (size_t)row0 * NB);
    float4* p1 = (float4*)(out + (size_t)(row0 + 1) * NB);
    float4 v0[4], v1[4];
#pragma unroll
    for (int q = 0; q < 4; q++) v0[q] = p0[tid + q * 256];
#pragma unroll
    for (int q = 0; q < 4; q++) v1[q] = p1[tid + q * 256];

    float s0 = 0.f, s1 = 0.f;
#pragma unroll
    for (int q = 0; q < 4; q++) {
        s0 += (v0[q].x + v0[q].y) + (v0[q].z + v0[q].w);
        s1 += (v1[q].x + v1[q].y) + (v1[q].z + v1[q].w);
    }
#pragma unroll
    for (int o = 16; o > 0; o >>= 1) {
        s0 += __shfl_xor_sync(0xffffffffu, s0, o);
        s1 += __shfl_xor_sync(0xffffffffu, s1, o);
    }
    if (lane == 0) { sred0[warp] = s0; sred1[warp] = s1; }
    __syncthreads();
    s0 = sred0[0] + sred0[1] + sred0[2] + sred0[3] +
         sred0[4] + sred0[5] + sred0[6] + sred0[7];
    s1 = sred1[0] + sred1[1] + sred1[2] + sred1[3] +
         sred1[4] + sred1[5] + sred1[6] + sred1[7];

    const float inv0 = 1.0f / s0;
    const float inv1 = 1.0f / s1;
#pragma unroll
    for (int q = 0; q < 4; q++) {
        v0[q].x *= inv0; v0[q].y *= inv0; v0[q].z *= inv0; v0[q].w *= inv0;
        p0[tid + q * 256] = v0[q];
    }
#pragma unroll
    for (int q = 0; q < 4; q++) {
        v1[q].x *= inv1; v1[q].y *= inv1; v1[q].z *= inv1; v1[q].w *= inv1;
        p1[tid + q * 256] = v1[q];
    }
}

// ---------------------------------------------------------------------------
// Launch
// ---------------------------------------------------------------------------
extern "C" void kernel_launch(void* const* d_in, const int* in_sizes, int n_in,
                              void* d_out, int out_size)
{
    (void)in_sizes; (void)n_in; (void)out_size;
    const float* qp = (const float*)d_in[0];
    const float* kp = (const float*)d_in[1];
    const float* Wq = (const float*)d_in[2];
    const float* bq = (const float*)d_in[3];
    const float* Wk = (const float*)d_in[4];
    const float* bk = (const float*)d_in[5];
    float* out = (float*)d_out;

    __nv_bfloat16 *qnh, *qnl, *knh, *knl;
    float *qsq, *ksq;
    cudaGetSymbolAddress((void**)&qnh, g_qn_hi);
    cudaGetSymbolAddress((void**)&qnl, g_qn_lo);
    cudaGetSymbolAddress((void**)&knh, g_kn_hi);
    cudaGetSymbolAddress((void**)&knl, g_kn_lo);
    cudaGetSymbolAddress((void**)&qsq, g_qsq);
    cudaGetSymbolAddress((void**)&ksq, g_ksq);

    cudaFuncSetAttribute(gram_exp_kernel,
                         cudaFuncAttributeMaxDynamicSharedMemorySize, GRAM_SMEM);

    dim3 gp(NB / RROWS, 2);
    proj_norm_kernel<<<gp, 128>>>(qp, Wq, bq, kp, Wk, bk,
                                  qnh, qnl, qsq, knh, knl, ksq);

    dim3 g(NB / 128, NB / 128);
    gram_exp_kernel<<<g, 256, GRAM_SMEM>>>(out);

    scale_kernel<<<NB / 2, 256>>>(out);
}

// round 5
// speedup vs baseline: 2.1449x; 1.1024x over previous
#include <cuda_runtime.h>
#include <cuda_fp16.h>
#include <math.h>
#include <stdint.h>

// Problem constants
#define NB 4096
#define ND 128
#define EPSF 1e-8f
#define TEMPF 11.313708498984761f   // sqrt(128)

// Scratch (device globals; no allocation allowed)
__device__ __half g_qn_hi[NB * ND];
__device__ __half g_qn_lo[NB * ND];
__device__ __half g_kn_hi[NB * ND];
__device__ float g_qsq[NB];
__device__ float g_ksq[NB];

// ---------------------------------------------------------------------------
// PTX helpers (base compute_103 — NO sm_103a-only instructions)
// ---------------------------------------------------------------------------
__device__ __forceinline__ uint32_t smem_u32(const void* p) {
    uint32_t a;
    asm("{ .reg .u64 t; cvta.to.shared.u64 t, %1; cvt.u32.u64 %0, t; }"
        : "=r"(a) : "l"(p));
    return a;
}

__device__ __forceinline__ void ldsm4(uint32_t* r, uint32_t addr) {
    asm volatile("ldmatrix.sync.aligned.m8n8.x4.shared.b16 {%0,%1,%2,%3}, [%4];"
                 : "=r"(r[0]), "=r"(r[1]), "=r"(r[2]), "=r"(r[3]) : "r"(addr));
}

__device__ __forceinline__ void mma_f16(float* c, const uint32_t* a,
                                        const uint32_t* b) {
    asm volatile(
        "mma.sync.aligned.m16n8k16.row.col.f32.f16.f16.f32 "
        "{%0,%1,%2,%3}, {%4,%5,%6,%7}, {%8,%9}, {%0,%1,%2,%3};"
        : "+f"(c[0]), "+f"(c[1]), "+f"(c[2]), "+f"(c[3])
        : "r"(a[0]), "r"(a[1]), "r"(a[2]), "r"(a[3]), "r"(b[0]), "r"(b[1]));
}

__device__ __forceinline__ void cp16(uint32_t s, const void* g) {
    asm volatile("cp.async.cg.shared.global [%0], [%1], 16;" :: "r"(s), "l"(g));
}
__device__ __forceinline__ void cp_commit() {
    asm volatile("cp.async.commit_group;" ::: "memory");
}
__device__ __forceinline__ void cp_wait1() {
    asm volatile("cp.async.wait_group 1;" ::: "memory");
}
__device__ __forceinline__ void cp_wait0() {
    asm volatile("cp.async.wait_group 0;" ::: "memory");
}

// ---------------------------------------------------------------------------
// Kernel A: projection + analytic metric-norm normalization (q/k via
// blockIdx.y). float4-vectorized; 256 threads; 16 rows/block.
// Thread: row-group g = tid>>7 (8 rows), output column c = tid&127.
// Emits fp16 hi/lo split of qn (and hi of kn; lo emitted for both, cheap)
// plus the squared norms.
// ---------------------------------------------------------------------------
#define PROWS 16

__global__ __launch_bounds__(256) void proj_norm_kernel(
    const float* __restrict__ Xq, const float* __restrict__ Wq,
    const float* __restrict__ bq,
    const float* __restrict__ Xk, const float* __restrict__ Wk,
    const float* __restrict__ bk,
    __half* __restrict__ qH, __half* __restrict__ qL, float* __restrict__ qSq,
    __half* __restrict__ kH, float* __restrict__ kSq)
{
    const int which = blockIdx.y;
    const float* X = which ? Xk : Xq;
    const float* W = which ? Wk : Wq;
    const float* bias = which ? bk : bq;

    __shared__ float sW[ND][36];       // 32-k chunk, row-contiguous + pad
    __shared__ float sX[PROWS][132];
    __shared__ float red[PROWS][128];
    __shared__ float srow[PROWS];

    const int tid = threadIdx.x;
    const int g = tid >> 7;            // 0/1: row group of 8
    const int c = tid & 127;           // output column
    const int i0 = blockIdx.x * PROWS;

    // load X tile (16 x 128)
#pragma unroll
    for (int it = 0; it < 2; it++) {
        const int idx = it * 256 + tid;
        const int r = idx >> 5, k4 = idx & 31;
        *(float4*)&sX[r][k4 * 4] = *(const float4*)&X[(i0 + r) * ND + k4 * 4];
    }

    const float bv = bias[c];

    float acc[8];
#pragma unroll
    for (int r = 0; r < 8; r++) acc[r] = 0.f;

    for (int kc = 0; kc < 4; kc++) {
        // load W chunk: rows 0..127 x 32 k-values
#pragma unroll
        for (int it = 0; it < 4; it++) {
            const int idx = it * 256 + tid;
            const int wc = idx >> 3, kk = idx & 7;
            *(float4*)&sW[wc][kk * 4] =
                *(const float4*)&W[wc * ND + kc * 32 + kk * 4];
        }
        __syncthreads();

#pragma unroll
        for (int k4 = 0; k4 < 8; k4++) {
            const float4 w4 = *(const float4*)&sW[c][k4 * 4];
#pragma unroll
            for (int r = 0; r < 8; r++) {
                const float4 x4 = *(const float4*)&sX[g * 8 + r][kc * 32 + k4 * 4];
                acc[r] += x4.x * w4.x + x4.y * w4.y + x4.z * w4.z + x4.w * w4.w;
            }
        }
        __syncthreads();
    }

#pragma unroll
    for (int r = 0; r < 8; r++) acc[r] += bv;

#pragma unroll
    for (int r = 0; r < 8; r++) red[g * 8 + r][c] = acc[r] * acc[r];
    __syncthreads();

    {
        const int w = tid >> 5, lane = tid & 31;
#pragma unroll
        for (int rr = 0; rr < 2; rr++) {
            const int r = w * 2 + rr;
            float v = red[r][lane] + red[r][lane + 32] +
                      red[r][lane + 64] + red[r][lane + 96];
#pragma unroll
            for (int o = 16; o > 0; o >>= 1)
                v += __shfl_xor_sync(0xffffffffu, v, o);
            if (lane == 0) srow[r] = v;
        }
    }
    __syncthreads();

#pragma unroll
    for (int r = 0; r < 8; r++) {
        const int row = g * 8 + r;
        const float s = srow[row];
        const float invD = 1.0f / (float)ND;
        const float fro = sqrtf(s * s * invD * invD + 2.0f * s * invD + (float)ND);
        const float qmq = (s * s * invD + s) / (fro + EPSF);
        const float inv = 1.0f / (sqrtf(qmq) + EPSF);
        const float v = acc[r] * inv;
        const __half h = __float2half(v);
        if (which) {
            kH[(i0 + row) * ND + c] = h;
            if (c == 0) kSq[i0 + row] = s * inv * inv;
        } else {
            const __half l = __float2half(v - __half2float(h));
            qH[(i0 + row) * ND + c] = h;
            qL[(i0 + row) * ND + c] = l;
            if (c == 0) qSq[i0 + row] = s * inv * inv;
        }
    }
}

// ---------------------------------------------------------------------------
// Kernel B: fp16 2-product compensated HMMA Gram + fused exp-logit epilogue.
// G = (q_hi + q_lo) @ k_hi^T  (fp32 accum; residual ~1e-4 incoherent)
// cp.async 2-stage pipeline, 3 matrices per stage (qhi, qlo, khi).
// CTA: 128x128 tile, 8 warps (4M x 2N), warp tile 32x64.
// ---------------------------------------------------------------------------
#define SSTRIDE 40                 // fp16 elems per smem row (80 B)
#define MAT_BYTES 10240            // 128 rows * 80 B
#define STAGE_BYTES (3 * MAT_BYTES)
#define GRAM_SMEM (2 * STAGE_BYTES)   // 61440

__device__ __forceinline__ void issue_chunk(uint32_t sbase, int st, int kc,
                                            int i0, int j0, int tid)
{
    const uint32_t stb = sbase + (uint32_t)(st * STAGE_BYTES);
#pragma unroll
    for (int it = 0; it < 2; it++) {
        const int t = it * 256 + tid;      // 0..511
        const int row = t >> 2;
        const int seg = t & 3;
        const uint32_t soff = (uint32_t)(row * 80 + seg * 16);
        const size_t gi = (size_t)(i0 + row) * ND + kc * 32 + seg * 8;
        const size_t gj = (size_t)(j0 + row) * ND + kc * 32 + seg * 8;
        cp16(stb + 0 * MAT_BYTES + soff, &g_qn_hi[gi]);
        cp16(stb + 1 * MAT_BYTES + soff, &g_qn_lo[gi]);
        cp16(stb + 2 * MAT_BYTES + soff, &g_kn_hi[gj]);
    }
}

__global__ __launch_bounds__(256, 2) void gram_exp_kernel(float* __restrict__ out)
{
    extern __shared__ __align__(16) char dsm[];
    __shared__ float ks_s[128];
    __shared__ float qs_s[128];

    const int tid = threadIdx.x;
    const int lane = tid & 31;
    const int w = tid >> 5;
    const int wm = w & 3;        // M quarter (32 rows)
    const int wn = w >> 2;       // N half (64 cols)
    const int i0 = blockIdx.y * 128;
    const int j0 = blockIdx.x * 128;

    if (tid < 128) ks_s[tid] = g_ksq[j0 + tid];
    else           qs_s[tid - 128] = g_qsq[i0 + tid - 128];

    const uint32_t sbase = smem_u32(dsm);

    issue_chunk(sbase, 0, 0, i0, j0, tid); cp_commit();
    issue_chunk(sbase, 1, 1, i0, j0, tid); cp_commit();

    float acc[2][8][4];
#pragma unroll
    for (int mt = 0; mt < 2; mt++)
#pragma unroll
        for (int n8 = 0; n8 < 8; n8++)
#pragma unroll
            for (int q = 0; q < 4; q++) acc[mt][n8][q] = 0.f;

    // ldmatrix lane address components
    const int a_row = lane & 15;
    const int a_kh = lane >> 4;
    const int b_n = (lane & 7) | ((lane >> 1) & 8);
    const int b_kh = (lane >> 3) & 1;

#pragma unroll
    for (int kc = 0; kc < 4; kc++) {
        if (kc < 3) cp_wait1(); else cp_wait0();
        __syncthreads();

        const uint32_t stb = sbase + (uint32_t)((kc & 1) * STAGE_BYTES);
        const uint32_t ashi = stb + 0 * MAT_BYTES;
        const uint32_t aslo = stb + 1 * MAT_BYTES;
        const uint32_t bshi = stb + 2 * MAT_BYTES;

#pragma unroll
        for (int ks = 0; ks < 2; ks++) {
            const int k0 = ks * 16;
            const uint32_t a_off =
                (uint32_t)(((wm * 32 + a_row) * SSTRIDE + k0 + a_kh * 8) * 2);
            const uint32_t b_off0 =
                (uint32_t)(((wn * 64 + b_n) * SSTRIDE + k0 + b_kh * 8) * 2);

            uint32_t ahi[2][4], alo[2][4], bf[4][4];
#pragma unroll
            for (int mt = 0; mt < 2; mt++) {
                ldsm4(ahi[mt], ashi + a_off + (uint32_t)(mt * 16 * SSTRIDE * 2));
                ldsm4(alo[mt], aslo + a_off + (uint32_t)(mt * 16 * SSTRIDE * 2));
            }
#pragma unroll
            for (int nt = 0; nt < 4; nt++)
                ldsm4(bf[nt], bshi + b_off0 + (uint32_t)(nt * 16 * SSTRIDE * 2));

#pragma unroll
            for (int mt = 0; mt < 2; mt++)
#pragma unroll
                for (int nt = 0; nt < 4; nt++) {
                    mma_f16(acc[mt][nt * 2 + 0], ahi[mt], &bf[nt][0]);
                    mma_f16(acc[mt][nt * 2 + 1], ahi[mt], &bf[nt][2]);
                    mma_f16(acc[mt][nt * 2 + 0], alo[mt], &bf[nt][0]);
                    mma_f16(acc[mt][nt * 2 + 1], alo[mt], &bf[nt][2]);
                }
        }
        __syncthreads();
        if (kc < 2) { issue_chunk(sbase, kc & 1, kc + 2, i0, j0, tid); cp_commit(); }
    }

    // Epilogue: C frag (m16n8): c0,c1 -> row lane/4, cols 2*(lane%4)+{0,1};
    //           c2,c3 -> row+8.
    const int rq = lane >> 2;
    const int cq = (lane & 3) * 2;
#pragma unroll
    for (int mt = 0; mt < 2; mt++) {
        const int rl0 = wm * 32 + mt * 16 + rq;
        const float qs0 = qs_s[rl0];
        const float qs1 = qs_s[rl0 + 8];
#pragma unroll
        for (int n8 = 0; n8 < 8; n8++) {
            const int cl = wn * 64 + n8 * 8 + cq;
            const float k0v = ks_s[cl], k1v = ks_s[cl + 1];
            const float* a = acc[mt][n8];

            float d00 = fmaxf(qs0 + k0v - 2.0f * a[0], 0.0f);
            float d01 = fmaxf(qs0 + k1v - 2.0f * a[1], 0.0f);
            float d10 = fmaxf(qs1 + k0v - 2.0f * a[2], 0.0f);
            float d11 = fmaxf(qs1 + k1v - 2.0f * a[3], 0.0f);

            float2 e0, e1;
            e0.x = __expf(TEMPF / (1.0f + sqrtf(d00)));
            e0.y = __expf(TEMPF / (1.0f + sqrtf(d01)));
            e1.x = __expf(TEMPF / (1.0f + sqrtf(d10)));
            e1.y = __expf(TEMPF / (1.0f + sqrtf(d11)));

            *(float2*)&out[(size_t)(i0 + rl0) * NB + j0 + cl] = e0;
            *(float2*)&out[(size_t)(i0 + rl0 + 8) * NB + j0 + cl] = e1;
        }
    }
}

// ---------------------------------------------------------------------------
// Kernel C: row sum + normalize, 2 rows per block (deep MLP for latency).
// ---------------------------------------------------------------------------
__global__ __launch_bounds__(256) void scale_kernel(float* __restrict__ out)
{
    __shared__ float sred0[8];
    __shared__ float sred1[8];
    const int row0 = blockIdx.x * 2;
    const int tid = threadIdx.x;
    const int lane = tid & 31, warp = tid >> 5;

    float4* p0 = (float4*)(out + (size_t)row0 * NB);
    float4* p1 = (float4*)(out + (size_t)(row0 + 1) * NB);
    float4 v0[4], v1[4];
#pragma unroll
    for (int q = 0; q < 4; q++) v0[q] = p0[tid + q * 256];
#pragma unroll
    for (int q = 0; q < 4; q++) v1[q] = p1[tid + q * 256];

    float s0 = 0.f, s1 = 0.f;
#pragma unroll
    for (int q = 0; q < 4; q++) {
        s0 += (v0[q].x + v0[q].y) + (v0[q].z + v0[q].w);
        s1 += (v1[q].x + v1[q].y) + (v1[q].z + v1[q].w);
    }
#pragma unroll
    for (int o = 16; o > 0; o >>= 1) {
        s0 += __shfl_xor_sync(0xffffffffu, s0, o);
        s1 += __shfl_xor_sync(0xffffffffu, s1, o);
    }
    if (lane == 0) { sred0[warp] = s0; sred1[warp] = s1; }
    __syncthreads();
    s0 = sred0[0] + sred0[1] + sred0[2] + sred0[3] +
         sred0[4] + sred0[5] + sred0[6] + sred0[7];
    s1 = sred1[0] + sred1[1] + sred1[2] + sred1[3] +
         sred1[4] + sred1[5] + sred1[6] + sred1[7];

    const float inv0 = 1.0f / s0;
    const float inv1 = 1.0f / s1;
#pragma unroll
    for (int q = 0; q < 4; q++) {
        v0[q].x *= inv0; v0[q].y *= inv0; v0[q].z *= inv0; v0[q].w *= inv0;
        p0[tid + q * 256] = v0[q];
    }
#pragma unroll
    for (int q = 0; q < 4; q++) {
        v1[q].x *= inv1; v1[q].y *= inv1; v1[q].z *= inv1; v1[q].w *= inv1;
        p1[tid + q * 256] = v1[q];
    }
}

// ---------------------------------------------------------------------------
// Launch
// ---------------------------------------------------------------------------
extern "C" void kernel_launch(void* const* d_in, const int* in_sizes, int n_in,
                              void* d_out, int out_size)
{
    (void)in_sizes; (void)n_in; (void)out_size;
    const float* qp = (const float*)d_in[0];
    const float* kp = (const float*)d_in[1];
    const float* Wq = (const float*)d_in[2];
    const float* bq = (const float*)d_in[3];
    const float* Wk = (const float*)d_in[4];
    const float* bk = (const float*)d_in[5];
    float* out = (float*)d_out;

    __half *qnh, *qnl, *knh;
    float *qsq, *ksq;
    cudaGetSymbolAddress((void**)&qnh, g_qn_hi);
    cudaGetSymbolAddress((void**)&qnl, g_qn_lo);
    cudaGetSymbolAddress((void**)&knh, g_kn_hi);
    cudaGetSymbolAddress((void**)&qsq, g_qsq);
    cudaGetSymbolAddress((void**)&ksq, g_ksq);

    cudaFuncSetAttribute(gram_exp_kernel,
                         cudaFuncAttributeMaxDynamicSharedMemorySize, GRAM_SMEM);

    dim3 gp(NB / PROWS, 2);
    proj_norm_kernel<<<gp, 256>>>(qp, Wq, bq, kp, Wk, bk,
                                  qnh, qnl, qsq, knh, ksq);

    dim3 g(NB / 128, NB / 128);
    gram_exp_kernel<<<g, 256, GRAM_SMEM>>>(out);

    scale_kernel<<<NB / 2, 256>>>(out);
}

// round 6
// speedup vs baseline: 2.3219x; 1.0825x over previous
#include <cuda_runtime.h>
#include <cuda_fp16.h>
#include <math.h>
#include <stdint.h>

// Problem constants
#define NB 4096
#define ND 128
#define EPSF 1e-8f
#define TEMPF 11.313708498984761f   // sqrt(128)

// Scratch (device globals; no allocation allowed)
__device__ __half g_xq_hi[NB * ND];
__device__ __half g_xq_lo[NB * ND];
__device__ __half g_xk_hi[NB * ND];
__device__ __half g_xk_lo[NB * ND];
__device__ __half g_wq_hi[ND * ND];
__device__ __half g_wq_lo[ND * ND];
__device__ __half g_wk_hi[ND * ND];
__device__ __half g_wk_lo[ND * ND];
__device__ __half g_qn_hi[NB * ND];
__device__ __half g_qn_lo[NB * ND];
__device__ __half g_kn_hi[NB * ND];
__device__ float g_qsq[NB];
__device__ float g_ksq[NB];

// ---------------------------------------------------------------------------
// PTX helpers (base compute_103 — NO sm_103a-only instructions)
// ---------------------------------------------------------------------------
__device__ __forceinline__ uint32_t smem_u32(const void* p) {
    uint32_t a;
    asm("{ .reg .u64 t; cvta.to.shared.u64 t, %1; cvt.u32.u64 %0, t; }"
        : "=r"(a) : "l"(p));
    return a;
}

__device__ __forceinline__ void ldsm4(uint32_t* r, uint32_t addr) {
    asm volatile("ldmatrix.sync.aligned.m8n8.x4.shared.b16 {%0,%1,%2,%3}, [%4];"
                 : "=r"(r[0]), "=r"(r[1]), "=r"(r[2]), "=r"(r[3]) : "r"(addr));
}

__device__ __forceinline__ void mma_f16(float* c, const uint32_t* a,
                                        const uint32_t* b) {
    asm volatile(
        "mma.sync.aligned.m16n8k16.row.col.f32.f16.f16.f32 "
        "{%0,%1,%2,%3}, {%4,%5,%6,%7}, {%8,%9}, {%0,%1,%2,%3};"
        : "+f"(c[0]), "+f"(c[1]), "+f"(c[2]), "+f"(c[3])
        : "r"(a[0]), "r"(a[1]), "r"(a[2]), "r"(a[3]), "r"(b[0]), "r"(b[1]));
}

__device__ __forceinline__ void cp16(uint32_t s, const void* g) {
    asm volatile("cp.async.cg.shared.global [%0], [%1], 16;" :: "r"(s), "l"(g));
}
__device__ __forceinline__ void cp_commit() {
    asm volatile("cp.async.commit_group;" ::: "memory");
}
__device__ __forceinline__ void cp_wait1() {
    asm volatile("cp.async.wait_group 1;" ::: "memory");
}
__device__ __forceinline__ void cp_wait0() {
    asm volatile("cp.async.wait_group 0;" ::: "memory");
}

__device__ __forceinline__ uint32_t pack_h2(__half a, __half b) {
    __half2 t(a, b);
    return *reinterpret_cast<uint32_t*>(&t);
}

// ---------------------------------------------------------------------------
// Kernel 0: fp32 -> fp16 hi/lo split of X (q,k) and W (q,k).
// float4 granularity; segments concatenated.
//   seg0: qp 131072 f4   seg1: kp 131072 f4   seg2: Wq 4096 f4   seg3: Wk 4096 f4
// total = 270336 float4s = 1056 blocks x 256 threads.
// ---------------------------------------------------------------------------
__global__ __launch_bounds__(256) void split_kernel(
    const float* __restrict__ qp, const float* __restrict__ kp,
    const float* __restrict__ Wq, const float* __restrict__ Wk)
{
    const int idx = blockIdx.x * 256 + threadIdx.x;
    const float* src;
    __half *hi, *lo;
    int off;
    if (idx < 131072)      { src = qp; hi = g_xq_hi; lo = g_xq_lo; off = idx; }
    else if (idx < 262144) { src = kp; hi = g_xk_hi; lo = g_xk_lo; off = idx - 131072; }
    else if (idx < 266240) { src = Wq; hi = g_wq_hi; lo = g_wq_lo; off = idx - 262144; }
    else                   { src = Wk; hi = g_wk_hi; lo = g_wk_lo; off = idx - 266240; }

    const float4 v = ((const float4*)src)[off];
    const __half h0 = __float2half(v.x), h1 = __float2half(v.y);
    const __half h2 = __float2half(v.z), h3 = __float2half(v.w);
    const __half l0 = __float2half(v.x - __half2float(h0));
    const __half l1 = __float2half(v.y - __half2float(h1));
    const __half l2 = __float2half(v.z - __half2float(h2));
    const __half l3 = __float2half(v.w - __half2float(h3));
    ((uint2*)hi)[off] = make_uint2(pack_h2(h0, h1), pack_h2(h2, h3));
    ((uint2*)lo)[off] = make_uint2(pack_h2(l0, l1), pack_h2(l2, l3));
}

// ---------------------------------------------------------------------------
// Shared tile-layout constants
// ---------------------------------------------------------------------------
#define SSTRIDE 40                 // fp16 elems per smem row (80 B)
#define MAT_BYTES 10240            // 128 rows * 80 B

// ---------------------------------------------------------------------------
// Kernel A: projection via compensated HMMA + analytic metric normalization.
// grid (32, 2): 32 row-blocks x {q,k}. 8 warps; warp w owns rows w*16..+15,
// all 128 output cols. q = Xhi*Whi + Xlo*Whi + Xhi*Wlo (+bias), then
// row-norm via shfl reduction, write fp16 hi/lo split (+ squared norms).
// ---------------------------------------------------------------------------
#define PSTAGE_BYTES (4 * MAT_BYTES)
#define PROJ_SMEM (2 * PSTAGE_BYTES)   // 81920

__device__ __forceinline__ void proj_issue(uint32_t sbase, int st, int kc,
                                           int i0, int which, int tid)
{
    const __half* xh = which ? g_xk_hi : g_xq_hi;
    const __half* xl = which ? g_xk_lo : g_xq_lo;
    const __half* wh = which ? g_wk_hi : g_wq_hi;
    const __half* wl = which ? g_wk_lo : g_wq_lo;
    const uint32_t stb = sbase + (uint32_t)(st * PSTAGE_BYTES);
#pragma unroll
    for (int it = 0; it < 2; it++) {
        const int t = it * 256 + tid;
        const int row = t >> 2;
        const int seg = t & 3;
        const uint32_t soff = (uint32_t)(row * 80 + seg * 16);
        const size_t gx = (size_t)(i0 + row) * ND + kc * 32 + seg * 8;
        const size_t gw = (size_t)row * ND + kc * 32 + seg * 8;
        cp16(stb + 0 * MAT_BYTES + soff, &xh[gx]);
        cp16(stb + 1 * MAT_BYTES + soff, &xl[gx]);
        cp16(stb + 2 * MAT_BYTES + soff, &wh[gw]);
        cp16(stb + 3 * MAT_BYTES + soff, &wl[gw]);
    }
}

__global__ __launch_bounds__(256) void proj_mma_kernel(
    const float* __restrict__ bq, const float* __restrict__ bk)
{
    extern __shared__ __align__(16) char dsm[];
    __shared__ float b_s[128];

    const int tid = threadIdx.x;
    const int lane = tid & 31;
    const int w = tid >> 5;
    const int which = blockIdx.y;
    const int i0 = blockIdx.x * 128;

    if (tid < 128) b_s[tid] = which ? bk[tid] : bq[tid];

    const uint32_t sbase = smem_u32(dsm);
    proj_issue(sbase, 0, 0, i0, which, tid); cp_commit();
    proj_issue(sbase, 1, 1, i0, which, tid); cp_commit();

    float acc[16][4];
#pragma unroll
    for (int n8 = 0; n8 < 16; n8++)
#pragma unroll
        for (int q = 0; q < 4; q++) acc[n8][q] = 0.f;

    const int a_row = lane & 15;
    const int a_kh = lane >> 4;
    const int b_n = (lane & 7) | ((lane >> 1) & 8);
    const int b_kh = (lane >> 3) & 1;

#pragma unroll
    for (int kc = 0; kc < 4; kc++) {
        if (kc < 3) cp_wait1(); else cp_wait0();
        __syncthreads();

        const uint32_t stb = sbase + (uint32_t)((kc & 1) * PSTAGE_BYTES);
        const uint32_t sxh = stb + 0 * MAT_BYTES;
        const uint32_t sxl = stb + 1 * MAT_BYTES;
        const uint32_t swh = stb + 2 * MAT_BYTES;
        const uint32_t swl = stb + 3 * MAT_BYTES;

#pragma unroll
        for (int ks = 0; ks < 2; ks++) {
            const int k0 = ks * 16;
            const uint32_t a_off =
                (uint32_t)(((w * 16 + a_row) * SSTRIDE + k0 + a_kh * 8) * 2);
            const uint32_t b_off =
                (uint32_t)((b_n * SSTRIDE + k0 + b_kh * 8) * 2);

            uint32_t xh[4], xl[4];
            ldsm4(xh, sxh + a_off);
            ldsm4(xl, sxl + a_off);
#pragma unroll
            for (int nt = 0; nt < 8; nt++) {
                uint32_t wh[4], wl[4];
                const uint32_t nto = (uint32_t)(nt * 16 * SSTRIDE * 2);
                ldsm4(wh, swh + b_off + nto);
                ldsm4(wl, swl + b_off + nto);
                mma_f16(acc[2 * nt + 0], xh, &wh[0]);
                mma_f16(acc[2 * nt + 1], xh, &wh[2]);
                mma_f16(acc[2 * nt + 0], xl, &wh[0]);
                mma_f16(acc[2 * nt + 1], xl, &wh[2]);
                mma_f16(acc[2 * nt + 0], xh, &wl[0]);
                mma_f16(acc[2 * nt + 1], xh, &wl[2]);
            }
        }
        __syncthreads();
        if (kc < 2) { proj_issue(sbase, kc & 1, kc + 2, i0, which, tid); cp_commit(); }
    }

    // bias add
    const int cq = (lane & 3) * 2;
#pragma unroll
    for (int n8 = 0; n8 < 16; n8++) {
        const float b0 = b_s[n8 * 8 + cq];
        const float b1 = b_s[n8 * 8 + cq + 1];
        acc[n8][0] += b0; acc[n8][1] += b1;
        acc[n8][2] += b0; acc[n8][3] += b1;
    }

    // row sums of squares (rows r0 = w*16 + lane/4, r1 = r0 + 8)
    float s0 = 0.f, s1 = 0.f;
#pragma unroll
    for (int n8 = 0; n8 < 16; n8++) {
        s0 += acc[n8][0] * acc[n8][0] + acc[n8][1] * acc[n8][1];
        s1 += acc[n8][2] * acc[n8][2] + acc[n8][3] * acc[n8][3];
    }
    s0 += __shfl_xor_sync(0xffffffffu, s0, 1);
    s0 += __shfl_xor_sync(0xffffffffu, s0, 2);
    s1 += __shfl_xor_sync(0xffffffffu, s1, 1);
    s1 += __shfl_xor_sync(0xffffffffu, s1, 2);

    const float invD = 1.0f / (float)ND;
    const float fro0 = sqrtf(s0 * s0 * invD * invD + 2.0f * s0 * invD + (float)ND);
    const float fro1 = sqrtf(s1 * s1 * invD * invD + 2.0f * s1 * invD + (float)ND);
    const float inv0 = 1.0f / (sqrtf((s0 * s0 * invD + s0) / (fro0 + EPSF)) + EPSF);
    const float inv1 = 1.0f / (sqrtf((s1 * s1 * invD + s1) / (fro1 + EPSF)) + EPSF);

    const int r0 = i0 + w * 16 + (lane >> 2);
    const int r1 = r0 + 8;

    if ((lane & 3) == 0) {
        float* sq = which ? g_ksq : g_qsq;
        sq[r0] = s0 * inv0 * inv0;
        sq[r1] = s1 * inv1 * inv1;
    }

    __half* outH = which ? g_kn_hi : g_qn_hi;
#pragma unroll
    for (int n8 = 0; n8 < 16; n8++) {
        const int col = n8 * 8 + cq;
        const float v00 = acc[n8][0] * inv0, v01 = acc[n8][1] * inv0;
        const float v10 = acc[n8][2] * inv1, v11 = acc[n8][3] * inv1;
        const __half h00 = __float2half(v00), h01 = __float2half(v01);
        const __half h10 = __float2half(v10), h11 = __float2half(v11);
        *(uint32_t*)&outH[(size_t)r0 * ND + col] = pack_h2(h00, h01);
        *(uint32_t*)&outH[(size_t)r1 * ND + col] = pack_h2(h10, h11);
        if (!which) {
            const __half l00 = __float2half(v00 - __half2float(h00));
            const __half l01 = __float2half(v01 - __half2float(h01));
            const __half l10 = __float2half(v10 - __half2float(h10));
            const __half l11 = __float2half(v11 - __half2float(h11));
            *(uint32_t*)&g_qn_lo[(size_t)r0 * ND + col] = pack_h2(l00, l01);
            *(uint32_t*)&g_qn_lo[(size_t)r1 * ND + col] = pack_h2(l10, l11);
        }
    }
}

// ---------------------------------------------------------------------------
// Kernel B: fp16 2-product compensated HMMA Gram + fused exp-logit epilogue.
// G = (q_hi + q_lo) @ k_hi^T  (fp32 accum). cp.async 2-stage pipeline.
// CTA: 128x128 tile, 8 warps (4M x 2N), warp tile 32x64.
// ---------------------------------------------------------------------------
#define STAGE_BYTES (3 * MAT_BYTES)
#define GRAM_SMEM (2 * STAGE_BYTES)   // 61440

__device__ __forceinline__ void issue_chunk(uint32_t sbase, int st, int kc,
                                            int i0, int j0, int tid)
{
    const uint32_t stb = sbase + (uint32_t)(st * STAGE_BYTES);
#pragma unroll
    for (int it = 0; it < 2; it++) {
        const int t = it * 256 + tid;
        const int row = t >> 2;
        const int seg = t & 3;
        const uint32_t soff = (uint32_t)(row * 80 + seg * 16);
        const size_t gi = (size_t)(i0 + row) * ND + kc * 32 + seg * 8;
        const size_t gj = (size_t)(j0 + row) * ND + kc * 32 + seg * 8;
        cp16(stb + 0 * MAT_BYTES + soff, &g_qn_hi[gi]);
        cp16(stb + 1 * MAT_BYTES + soff, &g_qn_lo[gi]);
        cp16(stb + 2 * MAT_BYTES + soff, &g_kn_hi[gj]);
    }
}

__global__ __launch_bounds__(256, 2) void gram_exp_kernel(float* __restrict__ out)
{
    extern __shared__ __align__(16) char dsm[];
    __shared__ float ks_s[128];
    __shared__ float qs_s[128];

    const int tid = threadIdx.x;
    const int lane = tid & 31;
    const int w = tid >> 5;
    const int wm = w & 3;
    const int wn = w >> 2;
    const int i0 = blockIdx.y * 128;
    const int j0 = blockIdx.x * 128;

    if (tid < 128) ks_s[tid] = g_ksq[j0 + tid];
    else           qs_s[tid - 128] = g_qsq[i0 + tid - 128];

    const uint32_t sbase = smem_u32(dsm);

    issue_chunk(sbase, 0, 0, i0, j0, tid); cp_commit();
    issue_chunk(sbase, 1, 1, i0, j0, tid); cp_commit();

    float acc[2][8][4];
#pragma unroll
    for (int mt = 0; mt < 2; mt++)
#pragma unroll
        for (int n8 = 0; n8 < 8; n8++)
#pragma unroll
            for (int q = 0; q < 4; q++) acc[mt][n8][q] = 0.f;

    const int a_row = lane & 15;
    const int a_kh = lane >> 4;
    const int b_n = (lane & 7) | ((lane >> 1) & 8);
    const int b_kh = (lane >> 3) & 1;

#pragma unroll
    for (int kc = 0; kc < 4; kc++) {
        if (kc < 3) cp_wait1(); else cp_wait0();
        __syncthreads();

        const uint32_t stb = sbase + (uint32_t)((kc & 1) * STAGE_BYTES);
        const uint32_t ashi = stb + 0 * MAT_BYTES;
        const uint32_t aslo = stb + 1 * MAT_BYTES;
        const uint32_t bshi = stb + 2 * MAT_BYTES;

#pragma unroll
        for (int ks = 0; ks < 2; ks++) {
            const int k0 = ks * 16;
            const uint32_t a_off =
                (uint32_t)(((wm * 32 + a_row) * SSTRIDE + k0 + a_kh * 8) * 2);
            const uint32_t b_off0 =
                (uint32_t)(((wn * 64 + b_n) * SSTRIDE + k0 + b_kh * 8) * 2);

            uint32_t ahi[2][4], alo[2][4], bf[4][4];
#pragma unroll
            for (int mt = 0; mt < 2; mt++) {
                ldsm4(ahi[mt], ashi + a_off + (uint32_t)(mt * 16 * SSTRIDE * 2));
                ldsm4(alo[mt], aslo + a_off + (uint32_t)(mt * 16 * SSTRIDE * 2));
            }
#pragma unroll
            for (int nt = 0; nt < 4; nt++)
                ldsm4(bf[nt], bshi + b_off0 + (uint32_t)(nt * 16 * SSTRIDE * 2));

#pragma unroll
            for (int mt = 0; mt < 2; mt++)
#pragma unroll
                for (int nt = 0; nt < 4; nt++) {
                    mma_f16(acc[mt][nt * 2 + 0], ahi[mt], &bf[nt][0]);
                    mma_f16(acc[mt][nt * 2 + 1], ahi[mt], &bf[nt][2]);
                    mma_f16(acc[mt][nt * 2 + 0], alo[mt], &bf[nt][0]);
                    mma_f16(acc[mt][nt * 2 + 1], alo[mt], &bf[nt][2]);
                }
        }
        __syncthreads();
        if (kc < 2) { issue_chunk(sbase, kc & 1, kc + 2, i0, j0, tid); cp_commit(); }
    }

    const int rq = lane >> 2;
    const int cq = (lane & 3) * 2;
#pragma unroll
    for (int mt = 0; mt < 2; mt++) {
        const int rl0 = wm * 32 + mt * 16 + rq;
        const float qs0 = qs_s[rl0];
        const float qs1 = qs_s[rl0 + 8];
#pragma unroll
        for (int n8 = 0; n8 < 8; n8++) {
            const int cl = wn * 64 + n8 * 8 + cq;
            const float k0v = ks_s[cl], k1v = ks_s[cl + 1];
            const float* a = acc[mt][n8];

            float d00 = fmaxf(qs0 + k0v - 2.0f * a[0], 0.0f);
            float d01 = fmaxf(qs0 + k1v - 2.0f * a[1], 0.0f);
            float d10 = fmaxf(qs1 + k0v - 2.0f * a[2], 0.0f);
            float d11 = fmaxf(qs1 + k1v - 2.0f * a[3], 0.0f);

            float2 e0, e1;
            e0.x = __expf(TEMPF / (1.0f + sqrtf(d00)));
            e0.y = __expf(TEMPF / (1.0f + sqrtf(d01)));
            e1.x = __expf(TEMPF / (1.0f + sqrtf(d10)));
            e1.y = __expf(TEMPF / (1.0f + sqrtf(d11)));

            *(float2*)&out[(size_t)(i0 + rl0) * NB + j0 + cl] = e0;
            *(float2*)&out[(size_t)(i0 + rl0 + 8) * NB + j0 + cl] = e1;
        }
    }
}

// ---------------------------------------------------------------------------
// Kernel C: row sum + normalize, 2 rows per block.
// ---------------------------------------------------------------------------
__global__ __launch_bounds__(256) void scale_kernel(float* __restrict__ out)
{
    __shared__ float sred0[8];
    __shared__ float sred1[8];
    const int row0 = blockIdx.x * 2;
    const int tid = threadIdx.x;
    const int lane = tid & 31, warp = tid >> 5;

    float4* p0 = (float4*)(out + (size_t)row0 * NB);
    float4* p1 = (float4*)(out + (size_t)(row0 + 1) * NB);
    float4 v0[4], v1[4];
#pragma unroll
    for (int q = 0; q < 4; q++) v0[q] = p0[tid + q * 256];
#pragma unroll
    for (int q = 0; q < 4; q++) v1[q] = p1[tid + q * 256];

    float s0 = 0.f, s1 = 0.f;
#pragma unroll
    for (int q = 0; q < 4; q++) {
        s0 += (v0[q].x + v0[q].y) + (v0[q].z + v0[q].w);
        s1 += (v1[q].x + v1[q].y) + (v1[q].z + v1[q].w);
    }
#pragma unroll
    for (int o = 16; o > 0; o >>= 1) {
        s0 += __shfl_xor_sync(0xffffffffu, s0, o);
        s1 += __shfl_xor_sync(0xffffffffu, s1, o);
    }
    if (lane == 0) { sred0[warp] = s0; sred1[warp] = s1; }
    __syncthreads();
    s0 = sred0[0] + sred0[1] + sred0[2] + sred0[3] +
         sred0[4] + sred0[5] + sred0[6] + sred0[7];
    s1 = sred1[0] + sred1[1] + sred1[2] + sred1[3] +
         sred1[4] + sred1[5] + sred1[6] + sred1[7];

    const float inv0 = 1.0f / s0;
    const float inv1 = 1.0f / s1;
#pragma unroll
    for (int q = 0; q < 4; q++) {
        v0[q].x *= inv0; v0[q].y *= inv0; v0[q].z *= inv0; v0[q].w *= inv0;
        p0[tid + q * 256] = v0[q];
    }
#pragma unroll
    for (int q = 0; q < 4; q++) {
        v1[q].x *= inv1; v1[q].y *= inv1; v1[q].z *= inv1; v1[q].w *= inv1;
        p1[tid + q * 256] = v1[q];
    }
}

// ---------------------------------------------------------------------------
// Launch
// ---------------------------------------------------------------------------
extern "C" void kernel_launch(void* const* d_in, const int* in_sizes, int n_in,
                              void* d_out, int out_size)
{
    (void)in_sizes; (void)n_in; (void)out_size;
    const float* qp = (const float*)d_in[0];
    const float* kp = (const float*)d_in[1];
    const float* Wq = (const float*)d_in[2];
    const float* bq = (const float*)d_in[3];
    const float* Wk = (const float*)d_in[4];
    const float* bk = (const float*)d_in[5];
    float* out = (float*)d_out;

    cudaFuncSetAttribute(proj_mma_kernel,
                         cudaFuncAttributeMaxDynamicSharedMemorySize, PROJ_SMEM);
    cudaFuncSetAttribute(gram_exp_kernel,
                         cudaFuncAttributeMaxDynamicSharedMemorySize, GRAM_SMEM);

    split_kernel<<<1056, 256>>>(qp, kp, Wq, Wk);

    dim3 gp(NB / 128, 2);
    proj_mma_kernel<<<gp, 256, PROJ_SMEM>>>(bq, bk);

    dim3 g(NB / 128, NB / 128);
    gram_exp_kernel<<<g, 256, GRAM_SMEM>>>(out);

    scale_kernel<<<NB / 2, 256>>>(out);
}

// round 7
// speedup vs baseline: 2.3299x; 1.0034x over previous
#include <cuda_runtime.h>
#include <cuda_fp16.h>
#include <math.h>
#include <stdint.h>

// Problem constants
#define NB 4096
#define ND 128
#define EPSF 1e-8f
#define TEMPF 11.313708498984761f   // sqrt(128)

// Scratch (device globals; no allocation allowed)
__device__ __half g_xq_hi[NB * ND];
__device__ __half g_xq_lo[NB * ND];
__device__ __half g_xk_hi[NB * ND];
__device__ __half g_xk_lo[NB * ND];
__device__ __half g_wq_hi[ND * ND];
__device__ __half g_wq_lo[ND * ND];
__device__ __half g_wk_hi[ND * ND];
__device__ __half g_wk_lo[ND * ND];
__device__ __half g_qn_hi[NB * ND];
__device__ __half g_qn_lo[NB * ND];
__device__ __half g_kn_hi[NB * ND];
__device__ float g_qsq[NB];
__device__ float g_ksq[NB];

// ---------------------------------------------------------------------------
// PTX helpers (base compute_103 — NO sm_103a-only instructions)
// ---------------------------------------------------------------------------
__device__ __forceinline__ uint32_t smem_u32(const void* p) {
    uint32_t a;
    asm("{ .reg .u64 t; cvta.to.shared.u64 t, %1; cvt.u32.u64 %0, t; }"
        : "=r"(a) : "l"(p));
    return a;
}

__device__ __forceinline__ void ldsm4(uint32_t* r, uint32_t addr) {
    asm volatile("ldmatrix.sync.aligned.m8n8.x4.shared.b16 {%0,%1,%2,%3}, [%4];"
                 : "=r"(r[0]), "=r"(r[1]), "=r"(r[2]), "=r"(r[3]) : "r"(addr));
}

__device__ __forceinline__ void mma_f16(float* c, const uint32_t* a,
                                        const uint32_t* b) {
    asm volatile(
        "mma.sync.aligned.m16n8k16.row.col.f32.f16.f16.f32 "
        "{%0,%1,%2,%3}, {%4,%5,%6,%7}, {%8,%9}, {%0,%1,%2,%3};"
        : "+f"(c[0]), "+f"(c[1]), "+f"(c[2]), "+f"(c[3])
        : "r"(a[0]), "r"(a[1]), "r"(a[2]), "r"(a[3]), "r"(b[0]), "r"(b[1]));
}

__device__ __forceinline__ void cp16(uint32_t s, const void* g) {
    asm volatile("cp.async.cg.shared.global [%0], [%1], 16;" :: "r"(s), "l"(g));
}
__device__ __forceinline__ void cp_commit() {
    asm volatile("cp.async.commit_group;" ::: "memory");
}
__device__ __forceinline__ void cp_wait1() {
    asm volatile("cp.async.wait_group 1;" ::: "memory");
}
__device__ __forceinline__ void cp_wait0() {
    asm volatile("cp.async.wait_group 0;" ::: "memory");
}

__device__ __forceinline__ uint32_t pack_h2(__half a, __half b) {
    __half2 t(a, b);
    return *reinterpret_cast<uint32_t*>(&t);
}

// ---------------------------------------------------------------------------
// Kernel 0: fp32 -> fp16 hi/lo split of X (q,k) and W (q,k).
// ---------------------------------------------------------------------------
__global__ __launch_bounds__(256) void split_kernel(
    const float* __restrict__ qp, const float* __restrict__ kp,
    const float* __restrict__ Wq, const float* __restrict__ Wk)
{
    const int idx = blockIdx.x * 256 + threadIdx.x;
    const float* src;
    __half *hi, *lo;
    int off;
    if (idx < 131072)      { src = qp; hi = g_xq_hi; lo = g_xq_lo; off = idx; }
    else if (idx < 262144) { src = kp; hi = g_xk_hi; lo = g_xk_lo; off = idx - 131072; }
    else if (idx < 266240) { src = Wq; hi = g_wq_hi; lo = g_wq_lo; off = idx - 262144; }
    else                   { src = Wk; hi = g_wk_hi; lo = g_wk_lo; off = idx - 266240; }

    const float4 v = ((const float4*)src)[off];
    const __half h0 = __float2half(v.x), h1 = __float2half(v.y);
    const __half h2 = __float2half(v.z), h3 = __float2half(v.w);
    const __half l0 = __float2half(v.x - __half2float(h0));
    const __half l1 = __float2half(v.y - __half2float(h1));
    const __half l2 = __float2half(v.z - __half2float(h2));
    const __half l3 = __float2half(v.w - __half2float(h3));
    ((uint2*)hi)[off] = make_uint2(pack_h2(h0, h1), pack_h2(h2, h3));
    ((uint2*)lo)[off] = make_uint2(pack_h2(l0, l1), pack_h2(l2, l3));
}

// ---------------------------------------------------------------------------
// Shared tile-layout constants
// ---------------------------------------------------------------------------
#define SSTRIDE 40                 // fp16 elems per smem row (80 B)
#define MAT_BYTES 10240            // 128 rows * 80 B

// ---------------------------------------------------------------------------
// Kernel A: projection via compensated HMMA + analytic metric normalization.
// MMA passes reordered so no accumulator is reused within < 16 MMAs.
// ---------------------------------------------------------------------------
#define PSTAGE_BYTES (4 * MAT_BYTES)
#define PROJ_SMEM (2 * PSTAGE_BYTES)   // 81920

__device__ __forceinline__ void proj_issue(uint32_t sbase, int st, int kc,
                                           int i0, int which, int tid)
{
    const __half* xh = which ? g_xk_hi : g_xq_hi;
    const __half* xl = which ? g_xk_lo : g_xq_lo;
    const __half* wh = which ? g_wk_hi : g_wq_hi;
    const __half* wl = which ? g_wk_lo : g_wq_lo;
    const uint32_t stb = sbase + (uint32_t)(st * PSTAGE_BYTES);
#pragma unroll
    for (int it = 0; it < 2; it++) {
        const int t = it * 256 + tid;
        const int row = t >> 2;
        const int seg = t & 3;
        const uint32_t soff = (uint32_t)(row * 80 + seg * 16);
        const size_t gx = (size_t)(i0 + row) * ND + kc * 32 + seg * 8;
        const size_t gw = (size_t)row * ND + kc * 32 + seg * 8;
        cp16(stb + 0 * MAT_BYTES + soff, &xh[gx]);
        cp16(stb + 1 * MAT_BYTES + soff, &xl[gx]);
        cp16(stb + 2 * MAT_BYTES + soff, &wh[gw]);
        cp16(stb + 3 * MAT_BYTES + soff, &wl[gw]);
    }
}

__global__ __launch_bounds__(256) void proj_mma_kernel(
    const float* __restrict__ bq, const float* __restrict__ bk)
{
    extern __shared__ __align__(16) char dsm[];
    __shared__ float b_s[128];

    const int tid = threadIdx.x;
    const int lane = tid & 31;
    const int w = tid >> 5;
    const int which = blockIdx.y;
    const int i0 = blockIdx.x * 128;

    if (tid < 128) b_s[tid] = which ? bk[tid] : bq[tid];

    const uint32_t sbase = smem_u32(dsm);
    proj_issue(sbase, 0, 0, i0, which, tid); cp_commit();
    proj_issue(sbase, 1, 1, i0, which, tid); cp_commit();

    float acc[16][4];
#pragma unroll
    for (int n8 = 0; n8 < 16; n8++)
#pragma unroll
        for (int q = 0; q < 4; q++) acc[n8][q] = 0.f;

    const int a_row = lane & 15;
    const int a_kh = lane >> 4;
    const int b_n = (lane & 7) | ((lane >> 1) & 8);
    const int b_kh = (lane >> 3) & 1;

#pragma unroll
    for (int kc = 0; kc < 4; kc++) {
        if (kc < 3) cp_wait1(); else cp_wait0();
        __syncthreads();

        const uint32_t stb = sbase + (uint32_t)((kc & 1) * PSTAGE_BYTES);
        const uint32_t sxh = stb + 0 * MAT_BYTES;
        const uint32_t sxl = stb + 1 * MAT_BYTES;
        const uint32_t swh = stb + 2 * MAT_BYTES;
        const uint32_t swl = stb + 3 * MAT_BYTES;

#pragma unroll
        for (int ks = 0; ks < 2; ks++) {
            const int k0 = ks * 16;
            const uint32_t a_off =
                (uint32_t)(((w * 16 + a_row) * SSTRIDE + k0 + a_kh * 8) * 2);
            const uint32_t b_off =
                (uint32_t)((b_n * SSTRIDE + k0 + b_kh * 8) * 2);

            uint32_t xh[4], xl[4], whr[8][4];
            ldsm4(xh, sxh + a_off);
            ldsm4(xl, sxl + a_off);

            // pass 1: xh * wh (load wh frags, keep them)
#pragma unroll
            for (int nt = 0; nt < 8; nt++) {
                ldsm4(whr[nt], swh + b_off + (uint32_t)(nt * 16 * SSTRIDE * 2));
                mma_f16(acc[2 * nt + 0], xh, &whr[nt][0]);
                mma_f16(acc[2 * nt + 1], xh, &whr[nt][2]);
            }
            // pass 2: xl * wh (reuse kept frags; distance >= 16)
#pragma unroll
            for (int nt = 0; nt < 8; nt++) {
                mma_f16(acc[2 * nt + 0], xl, &whr[nt][0]);
                mma_f16(acc[2 * nt + 1], xl, &whr[nt][2]);
            }
            // pass 3: xh * wl (reload wl; distance >= 16)
#pragma unroll
            for (int nt = 0; nt < 8; nt++) {
                uint32_t wl[4];
                ldsm4(wl, swl + b_off + (uint32_t)(nt * 16 * SSTRIDE * 2));
                mma_f16(acc[2 * nt + 0], xh, &wl[0]);
                mma_f16(acc[2 * nt + 1], xh, &wl[2]);
            }
        }
        __syncthreads();
        if (kc < 2) { proj_issue(sbase, kc & 1, kc + 2, i0, which, tid); cp_commit(); }
    }

    // bias add
    const int cq = (lane & 3) * 2;
#pragma unroll
    for (int n8 = 0; n8 < 16; n8++) {
        const float b0 = b_s[n8 * 8 + cq];
        const float b1 = b_s[n8 * 8 + cq + 1];
        acc[n8][0] += b0; acc[n8][1] += b1;
        acc[n8][2] += b0; acc[n8][3] += b1;
    }

    // row sums of squares (rows r0 = w*16 + lane/4, r1 = r0 + 8)
    float s0 = 0.f, s1 = 0.f;
#pragma unroll
    for (int n8 = 0; n8 < 16; n8++) {
        s0 += acc[n8][0] * acc[n8][0] + acc[n8][1] * acc[n8][1];
        s1 += acc[n8][2] * acc[n8][2] + acc[n8][3] * acc[n8][3];
    }
    s0 += __shfl_xor_sync(0xffffffffu, s0, 1);
    s0 += __shfl_xor_sync(0xffffffffu, s0, 2);
    s1 += __shfl_xor_sync(0xffffffffu, s1, 1);
    s1 += __shfl_xor_sync(0xffffffffu, s1, 2);

    const float invD = 1.0f / (float)ND;
    const float fro0 = sqrtf(s0 * s0 * invD * invD + 2.0f * s0 * invD + (float)ND);
    const float fro1 = sqrtf(s1 * s1 * invD * invD + 2.0f * s1 * invD + (float)ND);
    const float inv0 = 1.0f / (sqrtf((s0 * s0 * invD + s0) / (fro0 + EPSF)) + EPSF);
    const float inv1 = 1.0f / (sqrtf((s1 * s1 * invD + s1) / (fro1 + EPSF)) + EPSF);

    const int r0 = i0 + w * 16 + (lane >> 2);
    const int r1 = r0 + 8;

    if ((lane & 3) == 0) {
        float* sq = which ? g_ksq : g_qsq;
        sq[r0] = s0 * inv0 * inv0;
        sq[r1] = s1 * inv1 * inv1;
    }

    __half* outH = which ? g_kn_hi : g_qn_hi;
#pragma unroll
    for (int n8 = 0; n8 < 16; n8++) {
        const int col = n8 * 8 + cq;
        const float v00 = acc[n8][0] * inv0, v01 = acc[n8][1] * inv0;
        const float v10 = acc[n8][2] * inv1, v11 = acc[n8][3] * inv1;
        const __half h00 = __float2half(v00), h01 = __float2half(v01);
        const __half h10 = __float2half(v10), h11 = __float2half(v11);
        *(uint32_t*)&outH[(size_t)r0 * ND + col] = pack_h2(h00, h01);
        *(uint32_t*)&outH[(size_t)r1 * ND + col] = pack_h2(h10, h11);
        if (!which) {
            const __half l00 = __float2half(v00 - __half2float(h00));
            const __half l01 = __float2half(v01 - __half2float(h01));
            const __half l10 = __float2half(v10 - __half2float(h10));
            const __half l11 = __float2half(v11 - __half2float(h11));
            *(uint32_t*)&g_qn_lo[(size_t)r0 * ND + col] = pack_h2(l00, l01);
            *(uint32_t*)&g_qn_lo[(size_t)r1 * ND + col] = pack_h2(l10, l11);
        }
    }
}

// ---------------------------------------------------------------------------
// Kernel B: fp16 2-product compensated HMMA Gram + fused exp-logit epilogue.
// MMA loop split into hi-pass then lo-pass: accumulator reuse distance = 16.
// ---------------------------------------------------------------------------
#define STAGE_BYTES (3 * MAT_BYTES)
#define GRAM_SMEM (2 * STAGE_BYTES)   // 61440

__device__ __forceinline__ void issue_chunk(uint32_t sbase, int st, int kc,
                                            int i0, int j0, int tid)
{
    const uint32_t stb = sbase + (uint32_t)(st * STAGE_BYTES);
#pragma unroll
    for (int it = 0; it < 2; it++) {
        const int t = it * 256 + tid;
        const int row = t >> 2;
        const int seg = t & 3;
        const uint32_t soff = (uint32_t)(row * 80 + seg * 16);
        const size_t gi = (size_t)(i0 + row) * ND + kc * 32 + seg * 8;
        const size_t gj = (size_t)(j0 + row) * ND + kc * 32 + seg * 8;
        cp16(stb + 0 * MAT_BYTES + soff, &g_qn_hi[gi]);
        cp16(stb + 1 * MAT_BYTES + soff, &g_qn_lo[gi]);
        cp16(stb + 2 * MAT_BYTES + soff, &g_kn_hi[gj]);
    }
}

__global__ __launch_bounds__(256, 2) void gram_exp_kernel(float* __restrict__ out)
{
    extern __shared__ __align__(16) char dsm[];
    __shared__ float ks_s[128];
    __shared__ float qs_s[128];

    const int tid = threadIdx.x;
    const int lane = tid & 31;
    const int w = tid >> 5;
    const int wm = w & 3;
    const int wn = w >> 2;
    const int i0 = blockIdx.y * 128;
    const int j0 = blockIdx.x * 128;

    if (tid < 128) ks_s[tid] = g_ksq[j0 + tid];
    else           qs_s[tid - 128] = g_qsq[i0 + tid - 128];

    const uint32_t sbase = smem_u32(dsm);

    issue_chunk(sbase, 0, 0, i0, j0, tid); cp_commit();
    issue_chunk(sbase, 1, 1, i0, j0, tid); cp_commit();

    float acc[2][8][4];
#pragma unroll
    for (int mt = 0; mt < 2; mt++)
#pragma unroll
        for (int n8 = 0; n8 < 8; n8++)
#pragma unroll
            for (int q = 0; q < 4; q++) acc[mt][n8][q] = 0.f;

    const int a_row = lane & 15;
    const int a_kh = lane >> 4;
    const int b_n = (lane & 7) | ((lane >> 1) & 8);
    const int b_kh = (lane >> 3) & 1;

#pragma unroll
    for (int kc = 0; kc < 4; kc++) {
        if (kc < 3) cp_wait1(); else cp_wait0();
        __syncthreads();

        const uint32_t stb = sbase + (uint32_t)((kc & 1) * STAGE_BYTES);
        const uint32_t ashi = stb + 0 * MAT_BYTES;
        const uint32_t aslo = stb + 1 * MAT_BYTES;
        const uint32_t bshi = stb + 2 * MAT_BYTES;

#pragma unroll
        for (int ks = 0; ks < 2; ks++) {
            const int k0 = ks * 16;
            const uint32_t a_off =
                (uint32_t)(((wm * 32 + a_row) * SSTRIDE + k0 + a_kh * 8) * 2);
            const uint32_t b_off0 =
                (uint32_t)(((wn * 64 + b_n) * SSTRIDE + k0 + b_kh * 8) * 2);

            uint32_t ahi[2][4], alo[2][4], bf[4][4];
#pragma unroll
            for (int mt = 0; mt < 2; mt++) {
                ldsm4(ahi[mt], ashi + a_off + (uint32_t)(mt * 16 * SSTRIDE * 2));
                ldsm4(alo[mt], aslo + a_off + (uint32_t)(mt * 16 * SSTRIDE * 2));
            }
#pragma unroll
            for (int nt = 0; nt < 4; nt++)
                ldsm4(bf[nt], bshi + b_off0 + (uint32_t)(nt * 16 * SSTRIDE * 2));

            // hi pass: 16 MMAs, all distinct accumulators
#pragma unroll
            for (int mt = 0; mt < 2; mt++)
#pragma unroll
                for (int nt = 0; nt < 4; nt++) {
                    mma_f16(acc[mt][nt * 2 + 0], ahi[mt], &bf[nt][0]);
                    mma_f16(acc[mt][nt * 2 + 1], ahi[mt], &bf[nt][2]);
                }
            // lo pass: reuse distance 16
#pragma unroll
            for (int mt = 0; mt < 2; mt++)
#pragma unroll
                for (int nt = 0; nt < 4; nt++) {
                    mma_f16(acc[mt][nt * 2 + 0], alo[mt], &bf[nt][0]);
                    mma_f16(acc[mt][nt * 2 + 1], alo[mt], &bf[nt][2]);
                }
        }
        __syncthreads();
        if (kc < 2) { issue_chunk(sbase, kc & 1, kc + 2, i0, j0, tid); cp_commit(); }
    }

    const int rq = lane >> 2;
    const int cq = (lane & 3) * 2;
#pragma unroll
    for (int mt = 0; mt < 2; mt++) {
        const int rl0 = wm * 32 + mt * 16 + rq;
        const float qs0 = qs_s[rl0];
        const float qs1 = qs_s[rl0 + 8];
#pragma unroll
        for (int n8 = 0; n8 < 8; n8++) {
            const int cl = wn * 64 + n8 * 8 + cq;
            const float k0v = ks_s[cl], k1v = ks_s[cl + 1];
            const float* a = acc[mt][n8];

            float d00 = fmaxf(qs0 + k0v - 2.0f * a[0], 0.0f);
            float d01 = fmaxf(qs0 + k1v - 2.0f * a[1], 0.0f);
            float d10 = fmaxf(qs1 + k0v - 2.0f * a[2], 0.0f);
            float d11 = fmaxf(qs1 + k1v - 2.0f * a[3], 0.0f);

            float2 e0, e1;
            e0.x = __expf(TEMPF / (1.0f + sqrtf(d00)));
            e0.y = __expf(TEMPF / (1.0f + sqrtf(d01)));
            e1.x = __expf(TEMPF / (1.0f + sqrtf(d10)));
            e1.y = __expf(TEMPF / (1.0f + sqrtf(d11)));

            *(float2*)&out[(size_t)(i0 + rl0) * NB + j0 + cl] = e0;
            *(float2*)&out[(size_t)(i0 + rl0 + 8) * NB + j0 + cl] = e1;
        }
    }
}

// ---------------------------------------------------------------------------
// Kernel C: row sum + normalize. 512 threads, 2 rows per block (half each).
// ---------------------------------------------------------------------------
__global__ __launch_bounds__(512) void scale_kernel(float* __restrict__ out)
{
    __shared__ float sred[16];
    const int tid = threadIdx.x;
    const int half = tid >> 8;                 // 0/1 -> row
    const int t = tid & 255;
    const int lane = tid & 31, warp = tid >> 5;
    const int row = blockIdx.x * 2 + half;

    float4* p = (float4*)(out + (size_t)row * NB);
    float4 v[4];
#pragma unroll
    for (int q = 0; q < 4; q++) v[q] = p[t + q * 256];

    float s = 0.f;
#pragma unroll
    for (int q = 0; q < 4; q++)
        s += (v[q].x + v[q].y) + (v[q].z + v[q].w);
#pragma unroll
    for (int o = 16; o > 0; o >>= 1) s += __shfl_xor_sync(0xffffffffu, s, o);
    if (lane == 0) sred[warp] = s;
    __syncthreads();
    const int base = half * 8;
    s = sred[base + 0] + sred[base + 1] + sred[base + 2] + sred[base + 3] +
        sred[base + 4] + sred[base + 5] + sred[base + 6] + sred[base + 7];

    const float inv = 1.0f / s;
#pragma unroll
    for (int q = 0; q < 4; q++) {
        v[q].x *= inv; v[q].y *= inv; v[q].z *= inv; v[q].w *= inv;
        p[t + q * 256] = v[q];
    }
}

// ---------------------------------------------------------------------------
// Launch
// ---------------------------------------------------------------------------
extern "C" void kernel_launch(void* const* d_in, const int* in_sizes, int n_in,
                              void* d_out, int out_size)
{
    (void)in_sizes; (void)n_in; (void)out_size;
    const float* qp = (const float*)d_in[0];
    const float* kp = (const float*)d_in[1];
    const float* Wq = (const float*)d_in[2];
    const float* bq = (const float*)d_in[3];
    const float* Wk = (const float*)d_in[4];
    const float* bk = (const float*)d_in[5];
    float* out = (float*)d_out;

    cudaFuncSetAttribute(proj_mma_kernel,
                         cudaFuncAttributeMaxDynamicSharedMemorySize, PROJ_SMEM);
    cudaFuncSetAttribute(gram_exp_kernel,
                         cudaFuncAttributeMaxDynamicSharedMemorySize, GRAM_SMEM);

    split_kernel<<<1056, 256>>>(qp, kp, Wq, Wk);

    dim3 gp(NB / 128, 2);
    proj_mma_kernel<<<gp, 256, PROJ_SMEM>>>(bq, bk);

    dim3 g(NB / 128, NB / 128);
    gram_exp_kernel<<<g, 256, GRAM_SMEM>>>(out);

    scale_kernel<<<NB / 2, 512>>>(out);
}

// round 8
// speedup vs baseline: 2.6203x; 1.1246x over previous
#include <cuda_runtime.h>
#include <cuda_fp16.h>
#include <math.h>
#include <stdint.h>

// Problem constants
#define NB 4096
#define ND 128
#define EPSF 1e-8f
#define TEMPF 11.313708498984761f   // sqrt(128)

// Scratch (device globals; no allocation allowed)
__device__ __half g_xq_hi[NB * ND];
__device__ __half g_xq_lo[NB * ND];
__device__ __half g_xk_hi[NB * ND];
__device__ __half g_xk_lo[NB * ND];
__device__ __half g_wq_hi[ND * ND];
__device__ __half g_wq_lo[ND * ND];
__device__ __half g_wk_hi[ND * ND];
__device__ __half g_wk_lo[ND * ND];
__device__ __half g_qn_hi[NB * ND];
__device__ __half g_kn_hi[NB * ND];
__device__ float g_qsq[NB];
__device__ float g_ksq[NB];
__device__ float g_psum[NB * 64];   // per-(row, jblock-half) partial row sums

// ---------------------------------------------------------------------------
// PTX helpers (base compute_103 — NO sm_103a-only instructions)
// ---------------------------------------------------------------------------
__device__ __forceinline__ uint32_t smem_u32(const void* p) {
    uint32_t a;
    asm("{ .reg .u64 t; cvta.to.shared.u64 t, %1; cvt.u32.u64 %0, t; }"
        : "=r"(a) : "l"(p));
    return a;
}

__device__ __forceinline__ void ldsm4(uint32_t* r, uint32_t addr) {
    asm volatile("ldmatrix.sync.aligned.m8n8.x4.shared.b16 {%0,%1,%2,%3}, [%4];"
                 : "=r"(r[0]), "=r"(r[1]), "=r"(r[2]), "=r"(r[3]) : "r"(addr));
}

__device__ __forceinline__ void mma_f16(float* c, const uint32_t* a,
                                        const uint32_t* b) {
    asm volatile(
        "mma.sync.aligned.m16n8k16.row.col.f32.f16.f16.f32 "
        "{%0,%1,%2,%3}, {%4,%5,%6,%7}, {%8,%9}, {%0,%1,%2,%3};"
        : "+f"(c[0]), "+f"(c[1]), "+f"(c[2]), "+f"(c[3])
        : "r"(a[0]), "r"(a[1]), "r"(a[2]), "r"(a[3]), "r"(b[0]), "r"(b[1]));
}

__device__ __forceinline__ void cp16(uint32_t s, const void* g) {
    asm volatile("cp.async.cg.shared.global [%0], [%1], 16;" :: "r"(s), "l"(g));
}
__device__ __forceinline__ void cp_commit() {
    asm volatile("cp.async.commit_group;" ::: "memory");
}
__device__ __forceinline__ void cp_wait1() {
    asm volatile("cp.async.wait_group 1;" ::: "memory");
}
__device__ __forceinline__ void cp_wait0() {
    asm volatile("cp.async.wait_group 0;" ::: "memory");
}

__device__ __forceinline__ uint32_t pack_h2(__half a, __half b) {
    __half2 t(a, b);
    return *reinterpret_cast<uint32_t*>(&t);
}

// ---------------------------------------------------------------------------
// Kernel 0: fp32 -> fp16 hi/lo split of X (q,k) and W (q,k).
// ---------------------------------------------------------------------------
__global__ __launch_bounds__(256) void split_kernel(
    const float* __restrict__ qp, const float* __restrict__ kp,
    const float* __restrict__ Wq, const float* __restrict__ Wk)
{
    const int idx = blockIdx.x * 256 + threadIdx.x;
    const float* src;
    __half *hi, *lo;
    int off;
    if (idx < 131072)      { src = qp; hi = g_xq_hi; lo = g_xq_lo; off = idx; }
    else if (idx < 262144) { src = kp; hi = g_xk_hi; lo = g_xk_lo; off = idx - 131072; }
    else if (idx < 266240) { src = Wq; hi = g_wq_hi; lo = g_wq_lo; off = idx - 262144; }
    else                   { src = Wk; hi = g_wk_hi; lo = g_wk_lo; off = idx - 266240; }

    const float4 v = ((const float4*)src)[off];
    const __half h0 = __float2half(v.x), h1 = __float2half(v.y);
    const __half h2 = __float2half(v.z), h3 = __float2half(v.w);
    const __half l0 = __float2half(v.x - __half2float(h0));
    const __half l1 = __float2half(v.y - __half2float(h1));
    const __half l2 = __float2half(v.z - __half2float(h2));
    const __half l3 = __float2half(v.w - __half2float(h3));
    ((uint2*)hi)[off] = make_uint2(pack_h2(h0, h1), pack_h2(h2, h3));
    ((uint2*)lo)[off] = make_uint2(pack_h2(l0, l1), pack_h2(l2, l3));
}

// ---------------------------------------------------------------------------
// Shared tile-layout constants
// ---------------------------------------------------------------------------
#define SSTRIDE 40                 // fp16 elems per smem row (80 B)
#define MAT_BYTES 10240            // 128 rows * 80 B

// ---------------------------------------------------------------------------
// Kernel A: projection via compensated HMMA + analytic metric normalization.
// q = Xhi*Whi + Xlo*Whi + Xhi*Wlo (+bias); emits fp16 hi only + sq norms.
// ---------------------------------------------------------------------------
#define PSTAGE_BYTES (4 * MAT_BYTES)
#define PROJ_SMEM (2 * PSTAGE_BYTES)   // 81920

__device__ __forceinline__ void proj_issue(uint32_t sbase, int st, int kc,
                                           int i0, int which, int tid)
{
    const __half* xh = which ? g_xk_hi : g_xq_hi;
    const __half* xl = which ? g_xk_lo : g_xq_lo;
    const __half* wh = which ? g_wk_hi : g_wq_hi;
    const __half* wl = which ? g_wk_lo : g_wq_lo;
    const uint32_t stb = sbase + (uint32_t)(st * PSTAGE_BYTES);
#pragma unroll
    for (int it = 0; it < 2; it++) {
        const int t = it * 256 + tid;
        const int row = t >> 2;
        const int seg = t & 3;
        const uint32_t soff = (uint32_t)(row * 80 + seg * 16);
        const size_t gx = (size_t)(i0 + row) * ND + kc * 32 + seg * 8;
        const size_t gw = (size_t)row * ND + kc * 32 + seg * 8;
        cp16(stb + 0 * MAT_BYTES + soff, &xh[gx]);
        cp16(stb + 1 * MAT_BYTES + soff, &xl[gx]);
        cp16(stb + 2 * MAT_BYTES + soff, &wh[gw]);
        cp16(stb + 3 * MAT_BYTES + soff, &wl[gw]);
    }
}

__global__ __launch_bounds__(256) void proj_mma_kernel(
    const float* __restrict__ bq, const float* __restrict__ bk)
{
    extern __shared__ __align__(16) char dsm[];
    __shared__ float b_s[128];

    const int tid = threadIdx.x;
    const int lane = tid & 31;
    const int w = tid >> 5;
    const int which = blockIdx.y;
    const int i0 = blockIdx.x * 128;

    if (tid < 128) b_s[tid] = which ? bk[tid] : bq[tid];

    const uint32_t sbase = smem_u32(dsm);
    proj_issue(sbase, 0, 0, i0, which, tid); cp_commit();
    proj_issue(sbase, 1, 1, i0, which, tid); cp_commit();

    float acc[16][4];
#pragma unroll
    for (int n8 = 0; n8 < 16; n8++)
#pragma unroll
        for (int q = 0; q < 4; q++) acc[n8][q] = 0.f;

    const int a_row = lane & 15;
    const int a_kh = lane >> 4;
    const int b_n = (lane & 7) | ((lane >> 1) & 8);
    const int b_kh = (lane >> 3) & 1;

#pragma unroll
    for (int kc = 0; kc < 4; kc++) {
        if (kc < 3) cp_wait1(); else cp_wait0();
        __syncthreads();

        const uint32_t stb = sbase + (uint32_t)((kc & 1) * PSTAGE_BYTES);
        const uint32_t sxh = stb + 0 * MAT_BYTES;
        const uint32_t sxl = stb + 1 * MAT_BYTES;
        const uint32_t swh = stb + 2 * MAT_BYTES;
        const uint32_t swl = stb + 3 * MAT_BYTES;

#pragma unroll
        for (int ks = 0; ks < 2; ks++) {
            const int k0 = ks * 16;
            const uint32_t a_off =
                (uint32_t)(((w * 16 + a_row) * SSTRIDE + k0 + a_kh * 8) * 2);
            const uint32_t b_off =
                (uint32_t)((b_n * SSTRIDE + k0 + b_kh * 8) * 2);

            uint32_t xh[4], xl[4], whr[8][4];
            ldsm4(xh, sxh + a_off);
            ldsm4(xl, sxl + a_off);

#pragma unroll
            for (int nt = 0; nt < 8; nt++) {
                ldsm4(whr[nt], swh + b_off + (uint32_t)(nt * 16 * SSTRIDE * 2));
                mma_f16(acc[2 * nt + 0], xh, &whr[nt][0]);
                mma_f16(acc[2 * nt + 1], xh, &whr[nt][2]);
            }
#pragma unroll
            for (int nt = 0; nt < 8; nt++) {
                mma_f16(acc[2 * nt + 0], xl, &whr[nt][0]);
                mma_f16(acc[2 * nt + 1], xl, &whr[nt][2]);
            }
#pragma unroll
            for (int nt = 0; nt < 8; nt++) {
                uint32_t wl[4];
                ldsm4(wl, swl + b_off + (uint32_t)(nt * 16 * SSTRIDE * 2));
                mma_f16(acc[2 * nt + 0], xh, &wl[0]);
                mma_f16(acc[2 * nt + 1], xh, &wl[2]);
            }
        }
        __syncthreads();
        if (kc < 2) { proj_issue(sbase, kc & 1, kc + 2, i0, which, tid); cp_commit(); }
    }

    const int cq = (lane & 3) * 2;
#pragma unroll
    for (int n8 = 0; n8 < 16; n8++) {
        const float b0 = b_s[n8 * 8 + cq];
        const float b1 = b_s[n8 * 8 + cq + 1];
        acc[n8][0] += b0; acc[n8][1] += b1;
        acc[n8][2] += b0; acc[n8][3] += b1;
    }

    float s0 = 0.f, s1 = 0.f;
#pragma unroll
    for (int n8 = 0; n8 < 16; n8++) {
        s0 += acc[n8][0] * acc[n8][0] + acc[n8][1] * acc[n8][1];
        s1 += acc[n8][2] * acc[n8][2] + acc[n8][3] * acc[n8][3];
    }
    s0 += __shfl_xor_sync(0xffffffffu, s0, 1);
    s0 += __shfl_xor_sync(0xffffffffu, s0, 2);
    s1 += __shfl_xor_sync(0xffffffffu, s1, 1);
    s1 += __shfl_xor_sync(0xffffffffu, s1, 2);

    const float invD = 1.0f / (float)ND;
    const float fro0 = sqrtf(s0 * s0 * invD * invD + 2.0f * s0 * invD + (float)ND);
    const float fro1 = sqrtf(s1 * s1 * invD * invD + 2.0f * s1 * invD + (float)ND);
    const float inv0 = 1.0f / (sqrtf((s0 * s0 * invD + s0) / (fro0 + EPSF)) + EPSF);
    const float inv1 = 1.0f / (sqrtf((s1 * s1 * invD + s1) / (fro1 + EPSF)) + EPSF);

    const int r0 = i0 + w * 16 + (lane >> 2);
    const int r1 = r0 + 8;

    if ((lane & 3) == 0) {
        float* sq = which ? g_ksq : g_qsq;
        sq[r0] = s0 * inv0 * inv0;
        sq[r1] = s1 * inv1 * inv1;
    }

    __half* outH = which ? g_kn_hi : g_qn_hi;
#pragma unroll
    for (int n8 = 0; n8 < 16; n8++) {
        const int col = n8 * 8 + cq;
        *(uint32_t*)&outH[(size_t)r0 * ND + col] =
            pack_h2(__float2half(acc[n8][0] * inv0), __float2half(acc[n8][1] * inv0));
        *(uint32_t*)&outH[(size_t)r1 * ND + col] =
            pack_h2(__float2half(acc[n8][2] * inv1), __float2half(acc[n8][3] * inv1));
    }
}

// ---------------------------------------------------------------------------
// Kernel B: single-product fp16 HMMA Gram + fused exp-logit epilogue
// + per-warp partial row sums into g_psum.
// Stage = 2 matrices (qn_hi, kn_hi). CTA 128x128, 8 warps (4M x 2N).
// ---------------------------------------------------------------------------
#define STAGE_BYTES (2 * MAT_BYTES)
#define GRAM_SMEM (2 * STAGE_BYTES)   // 40960

__device__ __forceinline__ void issue_chunk(uint32_t sbase, int st, int kc,
                                            int i0, int j0, int tid)
{
    const uint32_t stb = sbase + (uint32_t)(st * STAGE_BYTES);
#pragma unroll
    for (int it = 0; it < 2; it++) {
        const int t = it * 256 + tid;
        const int row = t >> 2;
        const int seg = t & 3;
        const uint32_t soff = (uint32_t)(row * 80 + seg * 16);
        const size_t gi = (size_t)(i0 + row) * ND + kc * 32 + seg * 8;
        const size_t gj = (size_t)(j0 + row) * ND + kc * 32 + seg * 8;
        cp16(stb + 0 * MAT_BYTES + soff, &g_qn_hi[gi]);
        cp16(stb + 1 * MAT_BYTES + soff, &g_kn_hi[gj]);
    }
}

__global__ __launch_bounds__(256, 2) void gram_exp_kernel(float* __restrict__ out)
{
    extern __shared__ __align__(16) char dsm[];
    __shared__ float ks_s[128];
    __shared__ float qs_s[128];

    const int tid = threadIdx.x;
    const int lane = tid & 31;
    const int w = tid >> 5;
    const int wm = w & 3;
    const int wn = w >> 2;
    const int i0 = blockIdx.y * 128;
    const int j0 = blockIdx.x * 128;

    if (tid < 128) ks_s[tid] = g_ksq[j0 + tid];
    else           qs_s[tid - 128] = g_qsq[i0 + tid - 128];

    const uint32_t sbase = smem_u32(dsm);

    issue_chunk(sbase, 0, 0, i0, j0, tid); cp_commit();
    issue_chunk(sbase, 1, 1, i0, j0, tid); cp_commit();

    float acc[2][8][4];
#pragma unroll
    for (int mt = 0; mt < 2; mt++)
#pragma unroll
        for (int n8 = 0; n8 < 8; n8++)
#pragma unroll
            for (int q = 0; q < 4; q++) acc[mt][n8][q] = 0.f;

    const int a_row = lane & 15;
    const int a_kh = lane >> 4;
    const int b_n = (lane & 7) | ((lane >> 1) & 8);
    const int b_kh = (lane >> 3) & 1;

#pragma unroll
    for (int kc = 0; kc < 4; kc++) {
        if (kc < 3) cp_wait1(); else cp_wait0();
        __syncthreads();

        const uint32_t stb = sbase + (uint32_t)((kc & 1) * STAGE_BYTES);
        const uint32_t ashi = stb + 0 * MAT_BYTES;
        const uint32_t bshi = stb + 1 * MAT_BYTES;

#pragma unroll
        for (int ks = 0; ks < 2; ks++) {
            const int k0 = ks * 16;
            const uint32_t a_off =
                (uint32_t)(((wm * 32 + a_row) * SSTRIDE + k0 + a_kh * 8) * 2);
            const uint32_t b_off0 =
                (uint32_t)(((wn * 64 + b_n) * SSTRIDE + k0 + b_kh * 8) * 2);

            uint32_t ahi[2][4], bf[4][4];
#pragma unroll
            for (int mt = 0; mt < 2; mt++)
                ldsm4(ahi[mt], ashi + a_off + (uint32_t)(mt * 16 * SSTRIDE * 2));
#pragma unroll
            for (int nt = 0; nt < 4; nt++)
                ldsm4(bf[nt], bshi + b_off0 + (uint32_t)(nt * 16 * SSTRIDE * 2));

#pragma unroll
            for (int mt = 0; mt < 2; mt++)
#pragma unroll
                for (int nt = 0; nt < 4; nt++) {
                    mma_f16(acc[mt][nt * 2 + 0], ahi[mt], &bf[nt][0]);
                    mma_f16(acc[mt][nt * 2 + 1], ahi[mt], &bf[nt][2]);
                }
        }
        __syncthreads();
        if (kc < 2) { issue_chunk(sbase, kc & 1, kc + 2, i0, j0, tid); cp_commit(); }
    }

    // Epilogue + partial row sums.
    const int rq = lane >> 2;
    const int cq = (lane & 3) * 2;
    float rs[2][2];
    rs[0][0] = rs[0][1] = rs[1][0] = rs[1][1] = 0.f;

#pragma unroll
    for (int mt = 0; mt < 2; mt++) {
        const int rl0 = wm * 32 + mt * 16 + rq;
        const float qs0 = qs_s[rl0];
        const float qs1 = qs_s[rl0 + 8];
#pragma unroll
        for (int n8 = 0; n8 < 8; n8++) {
            const int cl = wn * 64 + n8 * 8 + cq;
            const float k0v = ks_s[cl], k1v = ks_s[cl + 1];
            const float* a = acc[mt][n8];

            float d00 = fmaxf(qs0 + k0v - 2.0f * a[0], 0.0f);
            float d01 = fmaxf(qs0 + k1v - 2.0f * a[1], 0.0f);
            float d10 = fmaxf(qs1 + k0v - 2.0f * a[2], 0.0f);
            float d11 = fmaxf(qs1 + k1v - 2.0f * a[3], 0.0f);

            float2 e0, e1;
            e0.x = __expf(TEMPF / (1.0f + sqrtf(d00)));
            e0.y = __expf(TEMPF / (1.0f + sqrtf(d01)));
            e1.x = __expf(TEMPF / (1.0f + sqrtf(d10)));
            e1.y = __expf(TEMPF / (1.0f + sqrtf(d11)));

            rs[mt][0] += e0.x + e0.y;
            rs[mt][1] += e1.x + e1.y;

            *(float2*)&out[(size_t)(i0 + rl0) * NB + j0 + cl] = e0;
            *(float2*)&out[(size_t)(i0 + rl0 + 8) * NB + j0 + cl] = e1;
        }
    }

    // Reduce partial sums over the 4 lanes sharing a row; store to g_psum.
#pragma unroll
    for (int mt = 0; mt < 2; mt++)
#pragma unroll
        for (int h = 0; h < 2; h++) {
            float s = rs[mt][h];
            s += __shfl_xor_sync(0xffffffffu, s, 1);
            s += __shfl_xor_sync(0xffffffffu, s, 2);
            if ((lane & 3) == 0) {
                const int row = i0 + wm * 32 + mt * 16 + rq + h * 8;
                g_psum[(size_t)row * 64 + blockIdx.x * 2 + wn] = s;
            }
        }
}

// ---------------------------------------------------------------------------
// Kernel C: normalize rows using precomputed partial sums. 512 thr / 2 rows.
// ---------------------------------------------------------------------------
__global__ __launch_bounds__(512) void scale_kernel(float* __restrict__ out)
{
    __shared__ float sinv[2];
    const int tid = threadIdx.x;
    const int half = tid >> 8;
    const int t = tid & 255;
    const int row = blockIdx.x * 2 + half;

    float4* p = (float4*)(out + (size_t)row * NB);
    float4 v[4];
#pragma unroll
    for (int q = 0; q < 4; q++) v[q] = p[t + q * 256];

    if (t < 32) {
        float s = g_psum[(size_t)row * 64 + t] + g_psum[(size_t)row * 64 + 32 + t];
#pragma unroll
        for (int o = 16; o > 0; o >>= 1) s += __shfl_xor_sync(0xffffffffu, s, o);
        if (t == 0) sinv[half] = 1.0f / s;
    }
    __syncthreads();
    const float inv = sinv[half];

#pragma unroll
    for (int q = 0; q < 4; q++) {
        v[q].x *= inv; v[q].y *= inv; v[q].z *= inv; v[q].w *= inv;
        p[t + q * 256] = v[q];
    }
}

// ---------------------------------------------------------------------------
// Launch
// ---------------------------------------------------------------------------
extern "C" void kernel_launch(void* const* d_in, const int* in_sizes, int n_in,
                              void* d_out, int out_size)
{
    (void)in_sizes; (void)n_in; (void)out_size;
    const float* qp = (const float*)d_in[0];
    const float* kp = (const float*)d_in[1];
    const float* Wq = (const float*)d_in[2];
    const float* bq = (const float*)d_in[3];
    const float* Wk = (const float*)d_in[4];
    const float* bk = (const float*)d_in[5];
    float* out = (float*)d_out;

    cudaFuncSetAttribute(proj_mma_kernel,
                         cudaFuncAttributeMaxDynamicSharedMemorySize, PROJ_SMEM);
    cudaFuncSetAttribute(gram_exp_kernel,
                         cudaFuncAttributeMaxDynamicSharedMemorySize, GRAM_SMEM);

    split_kernel<<<1056, 256>>>(qp, kp, Wq, Wk);

    dim3 gp(NB / 128, 2);
    proj_mma_kernel<<<gp, 256, PROJ_SMEM>>>(bq, bk);

    dim3 g(NB / 128, NB / 128);
    gram_exp_kernel<<<g, 256, GRAM_SMEM>>>(out);

    scale_kernel<<<NB / 2, 512>>>(out);
}